// round 2
// baseline (speedup 1.0000x reference)
#include <cuda_runtime.h>
#include <cuda_bf16.h>
#include <mma.h>
#include <cstdint>

using namespace nvcuda;

// ---------------- problem constants ----------------
constexpr int T_      = 2048;   // tokens
constexpr int DIM_    = 2048;
constexpr int INTER_  = 1408;
constexpr int SINTER_ = 2816;
constexpr int NE_     = 16;
constexpr int TOPK_   = 6;
constexpr int NPAIR   = T_ * TOPK_;      // 12288

// ---------------- tiling ----------------
constexpr int BM = 128;
constexpr int BN = 64;
constexpr int BK = 32;
constexpr int HROWS = NPAIR + NE_ * BM;  // padded H rows (per-expert tile padding)

// ---------------- device scratch (static, no allocation) ----------------
__device__ int   g_is64;
__device__ int   g_cnt[NE_];
__device__ int   g_offpad[NE_ + 1];
__device__ int   g_list[NE_ * NPAIR];
__device__ float g_H [(size_t)HROWS * INTER_];    // routed hidden (padded rows)
__device__ float g_Hs[(size_t)T_ * SINTER_];      // shared-expert hidden
__device__ float g_Yb[(size_t)NPAIR * DIM_];      // per-pair routed output (scaled)
__device__ float g_Z [(size_t)T_ * DIM_];         // shared-expert output

// ---------------- dtype probe: is `indices` int64 or int32? ----------------
// Values are in [0,16). If the buffer is little-endian int64, the odd 32-bit
// words of the first 128 entries are all zero; for int32 data they are random
// values in [0,16) (all-zero probability ~16^-128). Reads stay within the
// first 256 int32 slots, safe for both widths.
__global__ void detect_kernel(const int* __restrict__ idx32) {
    if (threadIdx.x == 0) {
        int a = 0;
        #pragma unroll 1
        for (int i = 0; i < 128; i++) a |= idx32[2 * i + 1];
        g_is64 = (a == 0) ? 1 : 0;
    }
}

// ---------------- deterministic per-expert pair lists ----------------
__global__ void build_lists(const int* __restrict__ idx32) {
    const int e = blockIdx.x;
    const bool is64 = (g_is64 != 0);
    __shared__ int wsum[8];
    __shared__ int sbase;
    const int tid = threadIdx.x, lane = tid & 31, w = tid >> 5;
    if (tid == 0) sbase = 0;
    __syncthreads();
    for (int st = 0; st < NPAIR; st += 256) {
        int p = st + tid;
        int v = is64 ? idx32[2 * p] : idx32[p];
        bool m = (v == e);
        unsigned bal = __ballot_sync(0xffffffffu, m);
        int within = __popc(bal & ((1u << lane) - 1u));
        if (lane == 0) wsum[w] = __popc(bal);
        __syncthreads();
        int off = sbase;
        for (int i = 0; i < w; i++) off += wsum[i];
        if (m) g_list[e * NPAIR + off + within] = p;
        __syncthreads();
        if (tid == 0) {
            int tot = 0;
            for (int i = 0; i < 8; i++) tot += wsum[i];
            sbase += tot;
        }
        __syncthreads();
    }
    if (tid == 0) g_cnt[e] = sbase;
}

__global__ void prefix_kernel() {
    if (threadIdx.x == 0) {
        int off = 0;
        for (int e = 0; e < NE_; e++) {
            g_offpad[e] = off;
            off += ((g_cnt[e] + BM - 1) / BM) * BM;
        }
        g_offpad[NE_] = off;
    }
}

// ---------------- wmma types ----------------
typedef wmma::fragment<wmma::matrix_a, 16, 16, 8, wmma::precision::tf32, wmma::row_major> FragA;
typedef wmma::fragment<wmma::matrix_b, 16, 16, 8, wmma::precision::tf32, wmma::row_major> FragB;
typedef wmma::fragment<wmma::accumulator, 16, 16, 8, float> FragC;

// ---------------- fused up-projection: H = silu(X@W1) * (X@W3) ----------------
// GATHER=true : routed experts, A rows gathered via per-expert pair list,
//               output rows go to the expert's padded region of g_H.
// GATHER=false: shared expert, dense rows, output g_Hs.
template<bool GATHER>
__global__ void __launch_bounds__(256, 1)
up_kernel(const float* __restrict__ X,
          const float* __restrict__ B1g,
          const float* __restrict__ B3g)
{
    constexpr int N = GATHER ? INTER_ : SINTER_;
    const int e = blockIdx.z;
    int cnt, hbase;
    if (GATHER) {
        cnt = g_cnt[e];
        if ((int)blockIdx.y * BM >= cnt) return;
        hbase = g_offpad[e] + blockIdx.y * BM;
    } else {
        cnt = T_;
        hbase = blockIdx.y * BM;
    }
    float* Hout = GATHER ? (float*)g_H : (float*)g_Hs;
    const int tile_m = blockIdx.y * BM;
    const int n0 = blockIdx.x * BN;
    const float* B1 = B1g + (size_t)e * DIM_ * N;
    const float* B3 = B3g + (size_t)e * DIM_ * N;

    __shared__ float sA [BM][BK + 4];
    __shared__ float sB1[BK][BN + 4];
    __shared__ float sB3[BK][BN + 4];

    const int tid  = threadIdx.x;
    const int warp = tid >> 5;
    const int wm   = warp & 3;   // 4 warps in M
    const int wn   = warp >> 2;  // 2 warps in N

    // A-row source pointers (gathered once, reused each K-tile)
    const float* arow[4];
    #pragma unroll
    for (int i = 0; i < 4; i++) {
        int r = (tid >> 3) + 32 * i;
        int row = tile_m + r;
        int tok;
        if (GATHER) tok = (row < cnt) ? (g_list[e * NPAIR + row] / TOPK_) : 0;
        else        tok = row;
        arow[i] = X + (size_t)tok * DIM_;
    }
    const int acol  = (tid & 7) * 4;
    const int brow0 = tid >> 4;
    const int bcol  = (tid & 15) * 4;

    FragC acc1[2][2], acc3[2][2];
    #pragma unroll
    for (int mi = 0; mi < 2; mi++)
        #pragma unroll
        for (int ni = 0; ni < 2; ni++) {
            wmma::fill_fragment(acc1[mi][ni], 0.f);
            wmma::fill_fragment(acc3[mi][ni], 0.f);
        }

    for (int k0 = 0; k0 < DIM_; k0 += BK) {
        #pragma unroll
        for (int i = 0; i < 4; i++) {
            float4 v = *(const float4*)(arow[i] + k0 + acol);
            int r = (tid >> 3) + 32 * i;
            sA[r][acol + 0] = wmma::__float_to_tf32(v.x);
            sA[r][acol + 1] = wmma::__float_to_tf32(v.y);
            sA[r][acol + 2] = wmma::__float_to_tf32(v.z);
            sA[r][acol + 3] = wmma::__float_to_tf32(v.w);
        }
        #pragma unroll
        for (int i = 0; i < 2; i++) {
            int r = brow0 + 16 * i;
            float4 v1 = *(const float4*)(B1 + (size_t)(k0 + r) * N + n0 + bcol);
            float4 v3 = *(const float4*)(B3 + (size_t)(k0 + r) * N + n0 + bcol);
            sB1[r][bcol + 0] = wmma::__float_to_tf32(v1.x);
            sB1[r][bcol + 1] = wmma::__float_to_tf32(v1.y);
            sB1[r][bcol + 2] = wmma::__float_to_tf32(v1.z);
            sB1[r][bcol + 3] = wmma::__float_to_tf32(v1.w);
            sB3[r][bcol + 0] = wmma::__float_to_tf32(v3.x);
            sB3[r][bcol + 1] = wmma::__float_to_tf32(v3.y);
            sB3[r][bcol + 2] = wmma::__float_to_tf32(v3.z);
            sB3[r][bcol + 3] = wmma::__float_to_tf32(v3.w);
        }
        __syncthreads();
        #pragma unroll
        for (int kk = 0; kk < BK; kk += 8) {
            FragA fa[2];
            FragB f1[2], f3[2];
            #pragma unroll
            for (int mi = 0; mi < 2; mi++)
                wmma::load_matrix_sync(fa[mi], &sA[wm * 32 + mi * 16][kk], BK + 4);
            #pragma unroll
            for (int ni = 0; ni < 2; ni++) {
                wmma::load_matrix_sync(f1[ni], &sB1[kk][wn * 32 + ni * 16], BN + 4);
                wmma::load_matrix_sync(f3[ni], &sB3[kk][wn * 32 + ni * 16], BN + 4);
            }
            #pragma unroll
            for (int mi = 0; mi < 2; mi++)
                #pragma unroll
                for (int ni = 0; ni < 2; ni++) {
                    wmma::mma_sync(acc1[mi][ni], fa[mi], f1[ni], acc1[mi][ni]);
                    wmma::mma_sync(acc3[mi][ni], fa[mi], f3[ni], acc3[mi][ni]);
                }
        }
        __syncthreads();
    }

    // epilogue: SiLU(a1) * a3, store to H (padded rows -> no guard needed)
    #pragma unroll
    for (int mi = 0; mi < 2; mi++)
        #pragma unroll
        for (int ni = 0; ni < 2; ni++) {
            FragC& a = acc1[mi][ni];
            FragC& b = acc3[mi][ni];
            #pragma unroll
            for (int t = 0; t < a.num_elements; t++) {
                float u = a.x[t];
                float s = u / (1.f + __expf(-u));
                a.x[t] = s * b.x[t];
            }
            wmma::store_matrix_sync(
                Hout + (size_t)(hbase + wm * 32 + mi * 16) * N + n0 + wn * 32 + ni * 16,
                a, N, wmma::mem_row_major);
        }
}

// ---------------- down-projection ----------------
// ROUTED=true : Y = H @ W2e, rows scattered by pair id and scaled by routing
//               weight into g_Yb (deterministic: one writer per pair).
// ROUTED=false: Z = Hs @ Ws2 dense into g_Z.
template<bool ROUTED>
__global__ void __launch_bounds__(256, 1)
down_kernel(const float* __restrict__ Bg, const float* __restrict__ wts)
{
    constexpr int K = ROUTED ? INTER_ : SINTER_;
    const int e = blockIdx.z;
    int cnt, abase;
    if (ROUTED) {
        cnt = g_cnt[e];
        if ((int)blockIdx.y * BM >= cnt) return;
        abase = g_offpad[e] + blockIdx.y * BM;
    } else {
        cnt = T_;
        abase = blockIdx.y * BM;
    }
    const float* Hin = ROUTED ? (const float*)g_H : (const float*)g_Hs;
    const int n0 = blockIdx.x * BN;
    const float* B = Bg + (size_t)e * K * DIM_;

    __shared__ float sA[BM][BK + 4];
    __shared__ float sB[BK][BN + 4];
    __shared__ float patch[8][16][36];

    const int tid  = threadIdx.x;
    const int warp = tid >> 5;
    const int wm   = warp & 3;
    const int wn   = warp >> 2;
    const int lane = tid & 31;

    const int acol  = (tid & 7) * 4;
    const int brow0 = tid >> 4;
    const int bcol  = (tid & 15) * 4;

    FragC acc[2][2];
    #pragma unroll
    for (int mi = 0; mi < 2; mi++)
        #pragma unroll
        for (int ni = 0; ni < 2; ni++) wmma::fill_fragment(acc[mi][ni], 0.f);

    for (int k0 = 0; k0 < K; k0 += BK) {
        #pragma unroll
        for (int i = 0; i < 4; i++) {
            int r = (tid >> 3) + 32 * i;
            float4 v = *(const float4*)(Hin + (size_t)(abase + r) * K + k0 + acol);
            sA[r][acol + 0] = wmma::__float_to_tf32(v.x);
            sA[r][acol + 1] = wmma::__float_to_tf32(v.y);
            sA[r][acol + 2] = wmma::__float_to_tf32(v.z);
            sA[r][acol + 3] = wmma::__float_to_tf32(v.w);
        }
        #pragma unroll
        for (int i = 0; i < 2; i++) {
            int r = brow0 + 16 * i;
            float4 v = *(const float4*)(B + (size_t)(k0 + r) * DIM_ + n0 + bcol);
            sB[r][bcol + 0] = wmma::__float_to_tf32(v.x);
            sB[r][bcol + 1] = wmma::__float_to_tf32(v.y);
            sB[r][bcol + 2] = wmma::__float_to_tf32(v.z);
            sB[r][bcol + 3] = wmma::__float_to_tf32(v.w);
        }
        __syncthreads();
        #pragma unroll
        for (int kk = 0; kk < BK; kk += 8) {
            FragA fa[2];
            FragB fb[2];
            #pragma unroll
            for (int mi = 0; mi < 2; mi++)
                wmma::load_matrix_sync(fa[mi], &sA[wm * 32 + mi * 16][kk], BK + 4);
            #pragma unroll
            for (int ni = 0; ni < 2; ni++)
                wmma::load_matrix_sync(fb[ni], &sB[kk][wn * 32 + ni * 16], BN + 4);
            #pragma unroll
            for (int mi = 0; mi < 2; mi++)
                #pragma unroll
                for (int ni = 0; ni < 2; ni++)
                    wmma::mma_sync(acc[mi][ni], fa[mi], fb[ni], acc[mi][ni]);
        }
        __syncthreads();
    }

    if (!ROUTED) {
        #pragma unroll
        for (int mi = 0; mi < 2; mi++)
            #pragma unroll
            for (int ni = 0; ni < 2; ni++)
                wmma::store_matrix_sync(
                    g_Z + (size_t)(abase + wm * 32 + mi * 16) * DIM_ + n0 + wn * 32 + ni * 16,
                    acc[mi][ni], DIM_, wmma::mem_row_major);
    } else {
        // scatter rows by pair id, scaled by routing weight
        #pragma unroll
        for (int mi = 0; mi < 2; mi++) {
            wmma::store_matrix_sync(&patch[warp][0][0],  acc[mi][0], 36, wmma::mem_row_major);
            wmma::store_matrix_sync(&patch[warp][0][16], acc[mi][1], 36, wmma::mem_row_major);
            __syncwarp();
            int r  = lane >> 1;
            int ch = (lane & 1) * 16;
            int slot = blockIdx.y * BM + wm * 32 + mi * 16 + r;
            if (slot < cnt) {
                int p = g_list[e * NPAIR + slot];
                float w = wts[p];
                float* dst = g_Yb + (size_t)p * DIM_ + n0 + wn * 32 + ch;
                #pragma unroll
                for (int c = 0; c < 16; c += 4) {
                    float4 v = *(float4*)&patch[warp][r][ch + c];
                    v.x *= w; v.y *= w; v.z *= w; v.w *= w;
                    *(float4*)(dst + c) = v;
                }
            }
            __syncwarp();
        }
    }
}

// ---------------- final reduction: out = sum_k Yb[t,k] + Z ----------------
__global__ void __launch_bounds__(256, 1) reduce_kernel(float* __restrict__ out) {
    int i = blockIdx.x * 256 + threadIdx.x;      // float4 index, total T_*DIM_/4
    const int row4 = DIM_ / 4;
    int t  = i / row4;
    int c4 = i % row4;
    float4 a = ((const float4*)g_Z)[i];
    #pragma unroll
    for (int k = 0; k < TOPK_; k++) {
        const float4 v = *(const float4*)(g_Yb + (size_t)(t * TOPK_ + k) * DIM_ + c4 * 4);
        a.x += v.x; a.y += v.y; a.z += v.z; a.w += v.w;
    }
    ((float4*)out)[i] = a;
}

// ---------------- launch ----------------
extern "C" void kernel_launch(void* const* d_in, const int* in_sizes, int n_in,
                              void* d_out, int out_size) {
    const float* x   = (const float*)d_in[0];
    const float* wts = (const float*)d_in[1];
    const int*   idx = (const int*)  d_in[2];
    const float* W1  = (const float*)d_in[3];
    const float* W3  = (const float*)d_in[4];
    const float* W2  = (const float*)d_in[5];
    const float* Ws1 = (const float*)d_in[6];
    const float* Ws3 = (const float*)d_in[7];
    const float* Ws2 = (const float*)d_in[8];
    float* out = (float*)d_out;

    detect_kernel<<<1, 32>>>(idx);
    build_lists<<<NE_, 256>>>(idx);
    prefix_kernel<<<1, 32>>>();

    // routed up: H = silu(X@W1e) * (X@W3e)   grid covers worst-case counts
    up_kernel<true><<<dim3(INTER_ / BN, NPAIR / BM, NE_), 256>>>(x, W1, W3);
    // shared up: Hs = silu(X@Ws1) * (X@Ws3)
    up_kernel<false><<<dim3(SINTER_ / BN, T_ / BM, 1), 256>>>(x, Ws1, Ws3);
    // routed down: Yb[pair] = w[pair] * (H @ W2e)
    down_kernel<true><<<dim3(DIM_ / BN, NPAIR / BM, NE_), 256>>>(W2, wts);
    // shared down: Z = Hs @ Ws2
    down_kernel<false><<<dim3(DIM_ / BN, T_ / BM, 1), 256>>>(Ws2, nullptr);
    // out[t] = sum_k Yb[t,k] + Z[t]
    reduce_kernel<<<(T_ * DIM_ / 4) / 256, 256>>>(out);
}

// round 3
// speedup vs baseline: 1.1615x; 1.1615x over previous
#include <cuda_runtime.h>
#include <cuda_bf16.h>
#include <mma.h>
#include <cstdint>

using namespace nvcuda;

// ---------------- problem constants ----------------
constexpr int T_      = 2048;
constexpr int DIM_    = 2048;
constexpr int INTER_  = 1408;
constexpr int SINTER_ = 2816;
constexpr int NE_     = 16;
constexpr int TOPK_   = 6;
constexpr int NPAIR   = T_ * TOPK_;      // 12288

// ---------------- tiling ----------------
constexpr int BM = 128;
constexpr int BN = 64;
constexpr int BK = 32;
constexpr int BK4 = BK + 4;              // padded A row stride (36 floats, 16B aligned)
constexpr int BN4 = BN + 4;              // padded B row stride (68 floats, 16B aligned)
constexpr int STAGES = 4;
constexpr int HROWS = NPAIR + NE_ * BM;

constexpr int UP_SMEM_FLTS   = STAGES * (BM * BK4 + 2 * BK * BN4);
constexpr int DOWN_SMEM_FLTS = STAGES * (BM * BK4 + BK * BN4);

// ---------------- device scratch ----------------
__device__ int   g_is64;
__device__ int   g_cnt[NE_];
__device__ int   g_offpad[NE_ + 1];
__device__ int   g_list[NE_ * NPAIR];
__device__ float g_H [(size_t)HROWS * INTER_];
__device__ float g_Hs[(size_t)T_ * SINTER_];
__device__ float g_Yb[(size_t)NPAIR * DIM_];
__device__ float g_Z [(size_t)T_ * DIM_];

// ---------------- cp.async helpers ----------------
__device__ __forceinline__ void cpa16(float* smem, const float* g) {
    unsigned saddr = (unsigned)__cvta_generic_to_shared(smem);
    asm volatile("cp.async.cg.shared.global [%0], [%1], 16;" :: "r"(saddr), "l"(g));
}
#define CP_COMMIT()  asm volatile("cp.async.commit_group;")
#define CP_WAIT(n)   asm volatile("cp.async.wait_group %0;" :: "n"(n))

// ---------------- dtype probe (int64 vs int32 indices) ----------------
__global__ void detect_kernel(const int* __restrict__ idx32) {
    if (threadIdx.x == 0) {
        int a = 0;
        #pragma unroll 1
        for (int i = 0; i < 128; i++) a |= idx32[2 * i + 1];
        g_is64 = (a == 0) ? 1 : 0;
    }
}

// ---------------- deterministic per-expert pair lists ----------------
__global__ void build_lists(const int* __restrict__ idx32) {
    const int e = blockIdx.x;
    const bool is64 = (g_is64 != 0);
    __shared__ int wsum[8];
    __shared__ int sbase;
    const int tid = threadIdx.x, lane = tid & 31, w = tid >> 5;
    if (tid == 0) sbase = 0;
    __syncthreads();
    for (int st = 0; st < NPAIR; st += 256) {
        int p = st + tid;
        int v = is64 ? idx32[2 * p] : idx32[p];
        bool m = (v == e);
        unsigned bal = __ballot_sync(0xffffffffu, m);
        int within = __popc(bal & ((1u << lane) - 1u));
        if (lane == 0) wsum[w] = __popc(bal);
        __syncthreads();
        int off = sbase;
        for (int i = 0; i < w; i++) off += wsum[i];
        if (m) g_list[e * NPAIR + off + within] = p;
        __syncthreads();
        if (tid == 0) {
            int tot = 0;
            for (int i = 0; i < 8; i++) tot += wsum[i];
            sbase += tot;
        }
        __syncthreads();
    }
    if (tid == 0) g_cnt[e] = sbase;
}

__global__ void prefix_kernel() {
    if (threadIdx.x == 0) {
        int off = 0;
        for (int e = 0; e < NE_; e++) {
            g_offpad[e] = off;
            off += ((g_cnt[e] + BM - 1) / BM) * BM;
        }
        g_offpad[NE_] = off;
    }
}

// ---------------- wmma types ----------------
typedef wmma::fragment<wmma::matrix_a, 16, 16, 8, wmma::precision::tf32, wmma::row_major> FragA;
typedef wmma::fragment<wmma::matrix_b, 16, 16, 8, wmma::precision::tf32, wmma::row_major> FragB;
typedef wmma::fragment<wmma::accumulator, 16, 16, 8, float> FragC;

template<class F>
__device__ __forceinline__ void to_tf32(F& f) {
    #pragma unroll
    for (int t = 0; t < f.num_elements; t++) f.x[t] = wmma::__float_to_tf32(f.x[t]);
}

// ---------------- fused up-projection: H = silu(X@W1) * (X@W3) ----------------
template<bool GATHER>
__global__ void __launch_bounds__(256, 1)
up_kernel(const float* __restrict__ X,
          const float* __restrict__ B1g,
          const float* __restrict__ B3g)
{
    constexpr int N  = GATHER ? INTER_ : SINTER_;
    constexpr int KT = DIM_ / BK;
    const int e = blockIdx.z;
    int cnt, hbase;
    if (GATHER) {
        cnt = g_cnt[e];
        if ((int)blockIdx.y * BM >= cnt) return;
        hbase = g_offpad[e] + blockIdx.y * BM;
    } else {
        cnt = T_;
        hbase = blockIdx.y * BM;
    }
    float* Hout = GATHER ? (float*)g_H : (float*)g_Hs;
    const int tile_m = blockIdx.y * BM;
    const int n0 = blockIdx.x * BN;
    const float* B1 = B1g + (size_t)e * DIM_ * N;
    const float* B3 = B3g + (size_t)e * DIM_ * N;

    extern __shared__ float smem[];
    float* sA  = smem;                              // [S][BM][BK4]
    float* sB1 = sA  + STAGES * BM * BK4;           // [S][BK][BN4]
    float* sB3 = sB1 + STAGES * BK * BN4;

    const int tid  = threadIdx.x;
    const int warp = tid >> 5;
    const int wm   = warp & 3;
    const int wn   = warp >> 2;

    // gathered A row pointers (fixed per block)
    const float* arow[4];
    #pragma unroll
    for (int i = 0; i < 4; i++) {
        int row = tile_m + (tid >> 3) + 32 * i;
        int tok;
        if (GATHER) tok = (row < cnt) ? (g_list[e * NPAIR + row] / TOPK_) : 0;
        else        tok = row;
        arow[i] = X + (size_t)tok * DIM_ + (tid & 7) * 4;
    }
    const int acol = (tid & 7) * 4;

    auto copy_stage = [&](int kt, int st) {
        const int k0 = kt * BK;
        #pragma unroll
        for (int i = 0; i < 4; i++) {
            int r = (tid >> 3) + 32 * i;
            cpa16(&sA[(st * BM + r) * BK4 + acol], arow[i] + k0);
        }
        #pragma unroll
        for (int i = 0; i < 2; i++) {
            int id = tid + 256 * i;
            int r  = id >> 4;
            int c  = (id & 15) * 4;
            cpa16(&sB1[(st * BK + r) * BN4 + c], B1 + (size_t)(k0 + r) * N + n0 + c);
            cpa16(&sB3[(st * BK + r) * BN4 + c], B3 + (size_t)(k0 + r) * N + n0 + c);
        }
    };

    FragC acc1[2][2], acc3[2][2];
    #pragma unroll
    for (int mi = 0; mi < 2; mi++)
        #pragma unroll
        for (int ni = 0; ni < 2; ni++) {
            wmma::fill_fragment(acc1[mi][ni], 0.f);
            wmma::fill_fragment(acc3[mi][ni], 0.f);
        }

    // preload STAGES-1 stages
    #pragma unroll
    for (int s = 0; s < STAGES - 1; s++) { copy_stage(s, s); CP_COMMIT(); }

    for (int kt = 0; kt < KT; kt++) {
        CP_WAIT(STAGES - 2);
        __syncthreads();
        int nk = kt + STAGES - 1;
        if (nk < KT) copy_stage(nk, nk % STAGES);
        CP_COMMIT();
        const int st = kt % STAGES;
        #pragma unroll
        for (int kk = 0; kk < BK; kk += 8) {
            FragA fa[2];
            FragB f1[2], f3[2];
            #pragma unroll
            for (int mi = 0; mi < 2; mi++) {
                wmma::load_matrix_sync(fa[mi], &sA[(st * BM + wm * 32 + mi * 16) * BK4 + kk], BK4);
                to_tf32(fa[mi]);
            }
            #pragma unroll
            for (int ni = 0; ni < 2; ni++) {
                wmma::load_matrix_sync(f1[ni], &sB1[(st * BK + kk) * BN4 + wn * 32 + ni * 16], BN4);
                wmma::load_matrix_sync(f3[ni], &sB3[(st * BK + kk) * BN4 + wn * 32 + ni * 16], BN4);
                to_tf32(f1[ni]);
                to_tf32(f3[ni]);
            }
            #pragma unroll
            for (int mi = 0; mi < 2; mi++)
                #pragma unroll
                for (int ni = 0; ni < 2; ni++) {
                    wmma::mma_sync(acc1[mi][ni], fa[mi], f1[ni], acc1[mi][ni]);
                    wmma::mma_sync(acc3[mi][ni], fa[mi], f3[ni], acc3[mi][ni]);
                }
        }
    }

    // epilogue: SiLU(a1) * a3 -> H (rows padded, no guard)
    #pragma unroll
    for (int mi = 0; mi < 2; mi++)
        #pragma unroll
        for (int ni = 0; ni < 2; ni++) {
            FragC& a = acc1[mi][ni];
            FragC& b = acc3[mi][ni];
            #pragma unroll
            for (int t = 0; t < a.num_elements; t++) {
                float u = a.x[t];
                float s = u / (1.f + __expf(-u));
                a.x[t] = s * b.x[t];
            }
            wmma::store_matrix_sync(
                Hout + (size_t)(hbase + wm * 32 + mi * 16) * N + n0 + wn * 32 + ni * 16,
                a, N, wmma::mem_row_major);
        }
}

// ---------------- down-projection ----------------
template<bool ROUTED>
__global__ void __launch_bounds__(256, 1)
down_kernel(const float* __restrict__ Bg, const float* __restrict__ wts)
{
    constexpr int K  = ROUTED ? INTER_ : SINTER_;
    constexpr int KT = K / BK;
    const int e = blockIdx.z;
    int cnt, abase;
    if (ROUTED) {
        cnt = g_cnt[e];
        if ((int)blockIdx.y * BM >= cnt) return;
        abase = g_offpad[e] + blockIdx.y * BM;
    } else {
        cnt = T_;
        abase = blockIdx.y * BM;
    }
    const float* Hin = ROUTED ? (const float*)g_H : (const float*)g_Hs;
    const int n0 = blockIdx.x * BN;
    const float* B = Bg + (size_t)e * K * DIM_;

    extern __shared__ float smem[];
    float* sA = smem;                       // [S][BM][BK4]
    float* sB = sA + STAGES * BM * BK4;     // [S][BK][BN4]

    const int tid  = threadIdx.x;
    const int warp = tid >> 5;
    const int wm   = warp & 3;
    const int wn   = warp >> 2;
    const int lane = tid & 31;
    const int acol = (tid & 7) * 4;
    const float* Arow = Hin + (size_t)(abase + (tid >> 3)) * K + acol;

    auto copy_stage = [&](int kt, int st) {
        const int k0 = kt * BK;
        #pragma unroll
        for (int i = 0; i < 4; i++) {
            int r = (tid >> 3) + 32 * i;
            cpa16(&sA[(st * BM + r) * BK4 + acol], Arow + (size_t)32 * i * K + k0);
        }
        #pragma unroll
        for (int i = 0; i < 2; i++) {
            int id = tid + 256 * i;
            int r  = id >> 4;
            int c  = (id & 15) * 4;
            cpa16(&sB[(st * BK + r) * BN4 + c], B + (size_t)(k0 + r) * DIM_ + n0 + c);
        }
    };

    FragC acc[2][2];
    #pragma unroll
    for (int mi = 0; mi < 2; mi++)
        #pragma unroll
        for (int ni = 0; ni < 2; ni++) wmma::fill_fragment(acc[mi][ni], 0.f);

    #pragma unroll
    for (int s = 0; s < STAGES - 1; s++) { copy_stage(s, s); CP_COMMIT(); }

    for (int kt = 0; kt < KT; kt++) {
        CP_WAIT(STAGES - 2);
        __syncthreads();
        int nk = kt + STAGES - 1;
        if (nk < KT) copy_stage(nk, nk % STAGES);
        CP_COMMIT();
        const int st = kt % STAGES;
        #pragma unroll
        for (int kk = 0; kk < BK; kk += 8) {
            FragA fa[2];
            FragB fb[2];
            #pragma unroll
            for (int mi = 0; mi < 2; mi++) {
                wmma::load_matrix_sync(fa[mi], &sA[(st * BM + wm * 32 + mi * 16) * BK4 + kk], BK4);
                to_tf32(fa[mi]);
            }
            #pragma unroll
            for (int ni = 0; ni < 2; ni++) {
                wmma::load_matrix_sync(fb[ni], &sB[(st * BK + kk) * BN4 + wn * 32 + ni * 16], BN4);
                to_tf32(fb[ni]);
            }
            #pragma unroll
            for (int mi = 0; mi < 2; mi++)
                #pragma unroll
                for (int ni = 0; ni < 2; ni++)
                    wmma::mma_sync(acc[mi][ni], fa[mi], fb[ni], acc[mi][ni]);
        }
    }

    if (!ROUTED) {
        #pragma unroll
        for (int mi = 0; mi < 2; mi++)
            #pragma unroll
            for (int ni = 0; ni < 2; ni++)
                wmma::store_matrix_sync(
                    g_Z + (size_t)(abase + wm * 32 + mi * 16) * DIM_ + n0 + wn * 32 + ni * 16,
                    acc[mi][ni], DIM_, wmma::mem_row_major);
    } else {
        // per-pair scatter with routing-weight scaling; reuse pipeline smem as patch
        __syncthreads();
        float* patch = smem + warp * 16 * 36;   // per-warp 16x36
        #pragma unroll
        for (int mi = 0; mi < 2; mi++) {
            wmma::store_matrix_sync(patch,      acc[mi][0], 36, wmma::mem_row_major);
            wmma::store_matrix_sync(patch + 16, acc[mi][1], 36, wmma::mem_row_major);
            __syncwarp();
            int r  = lane >> 1;
            int ch = (lane & 1) * 16;
            int slot = blockIdx.y * BM + wm * 32 + mi * 16 + r;
            if (slot < cnt) {
                int p = g_list[e * NPAIR + slot];
                float w = wts[p];
                float* dst = g_Yb + (size_t)p * DIM_ + n0 + wn * 32 + ch;
                #pragma unroll
                for (int c = 0; c < 16; c += 4) {
                    float4 v = *(float4*)&patch[r * 36 + ch + c];
                    v.x *= w; v.y *= w; v.z *= w; v.w *= w;
                    *(float4*)(dst + c) = v;
                }
            }
            __syncwarp();
        }
    }
}

// ---------------- final reduction: out = sum_k Yb[t,k] + Z ----------------
__global__ void __launch_bounds__(256, 1) reduce_kernel(float* __restrict__ out) {
    int i = blockIdx.x * 256 + threadIdx.x;
    const int row4 = DIM_ / 4;
    int t  = i / row4;
    int c4 = i % row4;
    float4 a = ((const float4*)g_Z)[i];
    #pragma unroll
    for (int k = 0; k < TOPK_; k++) {
        const float4 v = *(const float4*)(g_Yb + (size_t)(t * TOPK_ + k) * DIM_ + c4 * 4);
        a.x += v.x; a.y += v.y; a.z += v.z; a.w += v.w;
    }
    ((float4*)out)[i] = a;
}

// ---------------- launch ----------------
extern "C" void kernel_launch(void* const* d_in, const int* in_sizes, int n_in,
                              void* d_out, int out_size) {
    const float* x   = (const float*)d_in[0];
    const float* wts = (const float*)d_in[1];
    const int*   idx = (const int*)  d_in[2];
    const float* W1  = (const float*)d_in[3];
    const float* W3  = (const float*)d_in[4];
    const float* W2  = (const float*)d_in[5];
    const float* Ws1 = (const float*)d_in[6];
    const float* Ws3 = (const float*)d_in[7];
    const float* Ws2 = (const float*)d_in[8];
    float* out = (float*)d_out;

    const int upBytes   = UP_SMEM_FLTS   * 4;   // 143,360 B
    const int downBytes = DOWN_SMEM_FLTS * 4;   // 108,544 B
    cudaFuncSetAttribute(up_kernel<true>,    cudaFuncAttributeMaxDynamicSharedMemorySize, upBytes);
    cudaFuncSetAttribute(up_kernel<false>,   cudaFuncAttributeMaxDynamicSharedMemorySize, upBytes);
    cudaFuncSetAttribute(down_kernel<true>,  cudaFuncAttributeMaxDynamicSharedMemorySize, downBytes);
    cudaFuncSetAttribute(down_kernel<false>, cudaFuncAttributeMaxDynamicSharedMemorySize, downBytes);

    detect_kernel<<<1, 32>>>(idx);
    build_lists<<<NE_, 256>>>(idx);
    prefix_kernel<<<1, 32>>>();

    up_kernel<true ><<<dim3(INTER_  / BN, NPAIR / BM, NE_), 256, upBytes>>>(x, W1, W3);
    up_kernel<false><<<dim3(SINTER_ / BN, T_    / BM, 1  ), 256, upBytes>>>(x, Ws1, Ws3);
    down_kernel<true ><<<dim3(DIM_ / BN, NPAIR / BM, NE_), 256, downBytes>>>(W2, wts);
    down_kernel<false><<<dim3(DIM_ / BN, T_    / BM, 1  ), 256, downBytes>>>(Ws2, nullptr);
    reduce_kernel<<<(T_ * DIM_ / 4) / 256, 256>>>(out);
}

// round 9
// speedup vs baseline: 3.9718x; 3.4195x over previous
#include <cuda_runtime.h>
#include <cuda_fp16.h>
#include <mma.h>
#include <cstdint>

using namespace nvcuda;

// ---------------- problem constants ----------------
constexpr int T_      = 2048;
constexpr int DIM_    = 2048;
constexpr int INTER_  = 1408;
constexpr int SINTER_ = 2816;
constexpr int NE_     = 16;
constexpr int TOPK_   = 6;
constexpr int NPAIR   = T_ * TOPK_;      // 12288

// ---------------- tiling ----------------
constexpr int BM   = 128;
constexpr int BN   = 64;     // up: per B-matrix N tile (two matrices -> 128 total work)
constexpr int BND  = 128;    // down: N tile
constexpr int BK   = 32;     // K per stage (2 mma k-steps of 16)
constexpr int STAGES = 4;
constexpr int BKP  = BK  + 8;   // 40 halves (80B rows, LDSM-friendly pad)
constexpr int BNP  = BN  + 8;   // 72 halves
constexpr int BNDP = BND + 8;   // 136 halves
constexpr int HROWS = NPAIR + NE_ * BM;

constexpr int UP_SMEM_H   = STAGES * (BM * BKP + 2 * BK * BNP);  // 38912 halves = 77824 B
constexpr int DOWN_SMEM_H = STAGES * (BM * BKP + BK * BNDP);     // 37888 halves = 75776 B
constexpr int FP_UP   = 68;    // fuse-buffer float stride (up)
constexpr int FP_DN   = 132;   // patch float stride (down)

// ---------------- device scratch (static, no allocation) ----------------
__device__ int    g_is64;
__device__ int    g_cnt[NE_];
__device__ int    g_offpad[NE_ + 1];
__device__ int    g_list[NE_ * NPAIR];
__device__ __half g_W1h [(size_t)NE_ * DIM_ * INTER_];
__device__ __half g_W3h [(size_t)NE_ * DIM_ * INTER_];
__device__ __half g_W2h [(size_t)NE_ * INTER_ * DIM_];
__device__ __half g_Ws1h[(size_t)DIM_ * SINTER_];
__device__ __half g_Ws3h[(size_t)DIM_ * SINTER_];
__device__ __half g_Ws2h[(size_t)SINTER_ * DIM_];
__device__ __half g_Xh  [(size_t)T_ * DIM_];
__device__ __half g_Hh  [(size_t)HROWS * INTER_];
__device__ __half g_Hsh [(size_t)T_ * SINTER_];
__device__ float  g_Yb  [(size_t)NPAIR * DIM_];
__device__ float  g_Z   [(size_t)T_ * DIM_];

// ---------------- cp.async helpers ----------------
__device__ __forceinline__ void cpa16(__half* smem, const __half* g) {
    unsigned saddr = (unsigned)__cvta_generic_to_shared(smem);
    asm volatile("cp.async.cg.shared.global [%0], [%1], 16;" :: "r"(saddr), "l"(g));
}
#define CP_COMMIT()  asm volatile("cp.async.commit_group;")
#define CP_WAIT(n)   asm volatile("cp.async.wait_group %0;" :: "n"(n))

// ---------------- fp32 -> fp16 conversion prepass ----------------
__global__ void __launch_bounds__(256, 4) cvt_kernel(const float* __restrict__ s,
                                                     __half* __restrict__ d, int n) {
    int i = (blockIdx.x * 256 + threadIdx.x) * 8;
    if (i >= n) return;
    float4 a = *(const float4*)(s + i);
    float4 b = *(const float4*)(s + i + 4);
    __half2 h0 = __floats2half2_rn(a.x, a.y), h1 = __floats2half2_rn(a.z, a.w);
    __half2 h2 = __floats2half2_rn(b.x, b.y), h3 = __floats2half2_rn(b.z, b.w);
    uint4 o;
    o.x = *reinterpret_cast<unsigned*>(&h0);
    o.y = *reinterpret_cast<unsigned*>(&h1);
    o.z = *reinterpret_cast<unsigned*>(&h2);
    o.w = *reinterpret_cast<unsigned*>(&h3);
    *reinterpret_cast<uint4*>(d + i) = o;
}

// ---------------- dtype probe (int64 vs int32 indices) ----------------
__global__ void detect_kernel(const int* __restrict__ idx32) {
    if (threadIdx.x == 0) {
        int a = 0;
        #pragma unroll 1
        for (int i = 0; i < 128; i++) a |= idx32[2 * i + 1];
        g_is64 = (a == 0) ? 1 : 0;
    }
}

// ---------------- deterministic per-expert pair lists ----------------
__global__ void build_lists(const int* __restrict__ idx32) {
    const int e = blockIdx.x;
    const bool is64 = (g_is64 != 0);
    __shared__ int wsum[8];
    __shared__ int sbase;
    const int tid = threadIdx.x, lane = tid & 31, w = tid >> 5;
    if (tid == 0) sbase = 0;
    __syncthreads();
    for (int st = 0; st < NPAIR; st += 256) {
        int p = st + tid;
        int v = is64 ? idx32[2 * p] : idx32[p];
        bool m = (v == e);
        unsigned bal = __ballot_sync(0xffffffffu, m);
        int within = __popc(bal & ((1u << lane) - 1u));
        if (lane == 0) wsum[w] = __popc(bal);
        __syncthreads();
        int off = sbase;
        for (int i = 0; i < w; i++) off += wsum[i];
        if (m) g_list[e * NPAIR + off + within] = p;
        __syncthreads();
        if (tid == 0) {
            int tot = 0;
            for (int i = 0; i < 8; i++) tot += wsum[i];
            sbase += tot;
        }
        __syncthreads();
    }
    if (tid == 0) g_cnt[e] = sbase;
}

__global__ void prefix_kernel() {
    if (threadIdx.x == 0) {
        int off = 0;
        for (int e = 0; e < NE_; e++) {
            g_offpad[e] = off;
            off += ((g_cnt[e] + BM - 1) / BM) * BM;
        }
        g_offpad[NE_] = off;
    }
}

// ---------------- wmma types (fp16 in, fp32 accum) ----------------
typedef wmma::fragment<wmma::matrix_a, 16, 16, 16, __half, wmma::row_major> FA;
typedef wmma::fragment<wmma::matrix_b, 16, 16, 16, __half, wmma::row_major> FB;
typedef wmma::fragment<wmma::accumulator, 16, 16, 16, float> FC;

// =====================================================================
// up kernel: H = silu(X@W1) * (X@W3).  512 threads, 16 warps.
// warps 0-7 compute X@W1, warps 8-15 compute X@W3 on the same A tiles;
// fusion happens through an smem float buffer in the epilogue.
// =====================================================================
template<bool GATHER>
__global__ void __launch_bounds__(512, 1)
up_kernel()
{
    constexpr int N  = GATHER ? INTER_ : SINTER_;
    constexpr int KT = DIM_ / BK;     // 64
    const int e = blockIdx.z;
    int cnt, hbase;
    if (GATHER) {
        cnt = g_cnt[e];
        if ((int)blockIdx.y * BM >= cnt) return;
        hbase = g_offpad[e] + blockIdx.y * BM;
    } else {
        cnt = T_;
        hbase = blockIdx.y * BM;
    }
    __half* Hout = GATHER ? g_Hh : g_Hsh;
    const __half* B1 = GATHER ? (g_W1h + (size_t)e * DIM_ * N) : g_Ws1h;
    const __half* B3 = GATHER ? (g_W3h + (size_t)e * DIM_ * N) : g_Ws3h;
    const int n0 = blockIdx.x * BN;

    extern __shared__ __half sm[];
    __half* sA  = sm;                                  // [S][BM][BKP]
    __half* sB1 = sm + STAGES * BM * BKP;              // [S][BK][BNP]
    __half* sB3 = sB1 + STAGES * BK * BNP;

    const int tid  = threadIdx.x;
    const int warp = tid >> 5;
    const int grp  = warp >> 3;        // 0: W1, 1: W3
    const int wl   = warp & 7;
    const int wm   = wl & 3;           // 4 warps in M (32 rows each)
    const int wn   = wl >> 2;          // 2 warps in N (32 cols each)

    // ---- A chunk: one 16B chunk per thread (512 * 8 halves = 128x32)
    const int arow = tid >> 2;
    const int ac8  = (tid & 3) * 8;
    int tok;
    if (GATHER) {
        int row = blockIdx.y * BM + arow;
        tok = (row < cnt) ? (g_list[e * NPAIR + row] / TOPK_) : 0;
    } else {
        tok = blockIdx.y * BM + arow;
    }
    const __half* aptr = g_Xh + (size_t)tok * DIM_ + ac8;

    // ---- B chunk: threads 0-255 fill B1, 256-511 fill B3 (32x64 each)
    const int bmat = tid >> 8;
    const int bcn  = tid & 255;
    const int brow = bcn >> 3;
    const int bcol = (bcn & 7) * 8;
    const __half* bsrc = (bmat ? B3 : B1) + (size_t)brow * N + n0 + bcol;
    __half* bdst = bmat ? sB3 : sB1;

    auto copy_stage = [&](int kt, int st) {
        const int k0 = kt * BK;
        cpa16(&sA[(st * BM + arow) * BKP + ac8], aptr + k0);
        cpa16(&bdst[(st * BK + brow) * BNP + bcol], bsrc + (size_t)k0 * N);
    };

    FC acc[2][2];
    #pragma unroll
    for (int mi = 0; mi < 2; mi++)
        #pragma unroll
        for (int ni = 0; ni < 2; ni++) wmma::fill_fragment(acc[mi][ni], 0.f);

    const __half* sBg = grp ? sB3 : sB1;

    #pragma unroll
    for (int s = 0; s < STAGES - 1; s++) { copy_stage(s, s); CP_COMMIT(); }

    for (int kt = 0; kt < KT; kt++) {
        CP_WAIT(STAGES - 2);
        __syncthreads();
        int nk = kt + STAGES - 1;
        if (nk < KT) copy_stage(nk, nk % STAGES);
        CP_COMMIT();
        const int st = kt % STAGES;
        #pragma unroll
        for (int kk = 0; kk < BK; kk += 16) {
            FA fa[2];
            FB fb[2];
            #pragma unroll
            for (int mi = 0; mi < 2; mi++)
                wmma::load_matrix_sync(fa[mi], &sA[(st * BM + wm * 32 + mi * 16) * BKP + kk], BKP);
            #pragma unroll
            for (int ni = 0; ni < 2; ni++)
                wmma::load_matrix_sync(fb[ni], &sBg[(st * BK + kk) * BNP + wn * 32 + ni * 16], BNP);
            #pragma unroll
            for (int mi = 0; mi < 2; mi++)
                #pragma unroll
                for (int ni = 0; ni < 2; ni++)
                    wmma::mma_sync(acc[mi][ni], fa[mi], fb[ni], acc[mi][ni]);
        }
    }

    // ---- epilogue: dump both groups' accs to smem floats, fuse, store fp16 H
    CP_WAIT(0);
    __syncthreads();
    float* sF  = (float*)sm;                  // [2][BM][FP_UP]
    float* sFm = sF + grp * (BM * FP_UP);
    #pragma unroll
    for (int mi = 0; mi < 2; mi++)
        #pragma unroll
        for (int ni = 0; ni < 2; ni++)
            wmma::store_matrix_sync(&sFm[(wm * 32 + mi * 16) * FP_UP + wn * 32 + ni * 16],
                                    acc[mi][ni], FP_UP, wmma::mem_row_major);
    __syncthreads();

    {
        const int row = tid >> 2;
        const int seg = (tid & 3) * 16;
        const float* p1 = &sF[row * FP_UP + seg];
        const float* p3 = p1 + BM * FP_UP;
        __align__(16) __half hbuf[16];
        #pragma unroll
        for (int j = 0; j < 16; j++) {
            float u = p1[j];
            float s = u / (1.f + __expf(-u));
            hbuf[j] = __float2half_rn(s * p3[j]);
        }
        __half* dst = Hout + (size_t)(hbase + row) * N + n0 + seg;
        *(uint4*)(dst)     = *(uint4*)(hbuf);
        *(uint4*)(dst + 8) = *(uint4*)(hbuf + 8);
    }
}

// =====================================================================
// down kernel: Y = H @ W2.  512 threads, 16 warps (4x4), 128x128 tile.
// ROUTED: scatter rows by pair id scaled by routing weight into g_Yb.
// =====================================================================
template<bool ROUTED>
__global__ void __launch_bounds__(512, 1)
down_kernel(const float* __restrict__ wts)
{
    constexpr int K  = ROUTED ? INTER_ : SINTER_;
    constexpr int KT = K / BK;        // 44 or 88
    const int e = blockIdx.z;
    int cnt, abase;
    if (ROUTED) {
        cnt = g_cnt[e];
        if ((int)blockIdx.y * BM >= cnt) return;
        abase = g_offpad[e] + blockIdx.y * BM;
    } else {
        cnt = T_;
        abase = blockIdx.y * BM;
    }
    const __half* Hin = ROUTED ? g_Hh : g_Hsh;
    const __half* Bh  = ROUTED ? (g_W2h + (size_t)e * K * DIM_) : g_Ws2h;
    const int n0 = blockIdx.x * BND;

    extern __shared__ __half sm[];
    __half* sA = sm;                                // [S][BM][BKP]
    __half* sB = sm + STAGES * BM * BKP;            // [S][BK][BNDP]

    const int tid  = threadIdx.x;
    const int warp = tid >> 5;
    const int wm   = warp & 3;       // 4 warps in M
    const int wn   = warp >> 2;      // 4 warps in N

    const int arow = tid >> 2;
    const int ac8  = (tid & 3) * 8;
    const __half* aptr = Hin + (size_t)(abase + arow) * K + ac8;

    const int brow = tid >> 4;
    const int bcol = (tid & 15) * 8;
    const __half* bsrc = Bh + (size_t)brow * DIM_ + n0 + bcol;

    auto copy_stage = [&](int kt, int st) {
        const int k0 = kt * BK;
        cpa16(&sA[(st * BM + arow) * BKP + ac8], aptr + k0);
        cpa16(&sB[(st * BK + brow) * BNDP + bcol], bsrc + (size_t)k0 * DIM_);
    };

    FC acc[2][2];
    #pragma unroll
    for (int mi = 0; mi < 2; mi++)
        #pragma unroll
        for (int ni = 0; ni < 2; ni++) wmma::fill_fragment(acc[mi][ni], 0.f);

    #pragma unroll
    for (int s = 0; s < STAGES - 1; s++) { copy_stage(s, s); CP_COMMIT(); }

    for (int kt = 0; kt < KT; kt++) {
        CP_WAIT(STAGES - 2);
        __syncthreads();
        int nk = kt + STAGES - 1;
        if (nk < KT) copy_stage(nk, nk % STAGES);
        CP_COMMIT();
        const int st = kt % STAGES;
        #pragma unroll
        for (int kk = 0; kk < BK; kk += 16) {
            FA fa[2];
            FB fb[2];
            #pragma unroll
            for (int mi = 0; mi < 2; mi++)
                wmma::load_matrix_sync(fa[mi], &sA[(st * BM + wm * 32 + mi * 16) * BKP + kk], BKP);
            #pragma unroll
            for (int ni = 0; ni < 2; ni++)
                wmma::load_matrix_sync(fb[ni], &sB[(st * BK + kk) * BNDP + wn * 32 + ni * 16], BNDP);
            #pragma unroll
            for (int mi = 0; mi < 2; mi++)
                #pragma unroll
                for (int ni = 0; ni < 2; ni++)
                    wmma::mma_sync(acc[mi][ni], fa[mi], fb[ni], acc[mi][ni]);
        }
    }

    // ---- epilogue: dump to smem floats, then coalesced scatter/store
    CP_WAIT(0);
    __syncthreads();
    float* sF = (float*)sm;                   // [BM][FP_DN]
    #pragma unroll
    for (int mi = 0; mi < 2; mi++)
        #pragma unroll
        for (int ni = 0; ni < 2; ni++)
            wmma::store_matrix_sync(&sF[(wm * 32 + mi * 16) * FP_DN + wn * 32 + ni * 16],
                                    acc[mi][ni], FP_DN, wmma::mem_row_major);
    __syncthreads();

    {
        const int row = tid >> 2;
        const int seg = (tid & 3) * 32;
        const float* src = &sF[row * FP_DN + seg];
        if (ROUTED) {
            int gslot = blockIdx.y * BM + row;
            if (gslot < cnt) {
                int p = g_list[e * NPAIR + gslot];
                float w = wts[p];
                float* dst = g_Yb + (size_t)p * DIM_ + n0 + seg;
                #pragma unroll
                for (int j = 0; j < 32; j += 4) {
                    float4 v = *(const float4*)(src + j);
                    v.x *= w; v.y *= w; v.z *= w; v.w *= w;
                    *(float4*)(dst + j) = v;
                }
            }
        } else {
            float* dst = g_Z + (size_t)(abase + row) * DIM_ + n0 + seg;
            #pragma unroll
            for (int j = 0; j < 32; j += 4)
                *(float4*)(dst + j) = *(const float4*)(src + j);
        }
    }
}

// ---------------- final reduction: out = sum_k Yb[t,k] + Z ----------------
__global__ void __launch_bounds__(256, 1) reduce_kernel(float* __restrict__ out) {
    int i = blockIdx.x * 256 + threadIdx.x;
    const int row4 = DIM_ / 4;
    int t  = i / row4;
    int c4 = i % row4;
    float4 a = ((const float4*)g_Z)[i];
    #pragma unroll
    for (int k = 0; k < TOPK_; k++) {
        const float4 v = *(const float4*)(g_Yb + (size_t)(t * TOPK_ + k) * DIM_ + c4 * 4);
        a.x += v.x; a.y += v.y; a.z += v.z; a.w += v.w;
    }
    ((float4*)out)[i] = a;
}

// ---------------- launch ----------------
extern "C" void kernel_launch(void* const* d_in, const int* in_sizes, int n_in,
                              void* d_out, int out_size) {
    const float* x   = (const float*)d_in[0];
    const float* wts = (const float*)d_in[1];
    const int*   idx = (const int*)  d_in[2];
    const float* W1  = (const float*)d_in[3];
    const float* W3  = (const float*)d_in[4];
    const float* W2  = (const float*)d_in[5];
    const float* Ws1 = (const float*)d_in[6];
    const float* Ws3 = (const float*)d_in[7];
    const float* Ws2 = (const float*)d_in[8];
    float* out = (float*)d_out;

    const int upBytes   = UP_SMEM_H   * 2;   // 77,824
    const int downBytes = DOWN_SMEM_H * 2;   // 75,776
    cudaFuncSetAttribute(up_kernel<true>,    cudaFuncAttributeMaxDynamicSharedMemorySize, upBytes);
    cudaFuncSetAttribute(up_kernel<false>,   cudaFuncAttributeMaxDynamicSharedMemorySize, upBytes);
    cudaFuncSetAttribute(down_kernel<true>,  cudaFuncAttributeMaxDynamicSharedMemorySize, downBytes);
    cudaFuncSetAttribute(down_kernel<false>, cudaFuncAttributeMaxDynamicSharedMemorySize, downBytes);

    // fp16 scratch addresses (host query of device symbols; no allocation)
    void *pW1h, *pW3h, *pW2h, *pWs1h, *pWs3h, *pWs2h, *pXh;
    cudaGetSymbolAddress(&pW1h,  g_W1h);
    cudaGetSymbolAddress(&pW3h,  g_W3h);
    cudaGetSymbolAddress(&pW2h,  g_W2h);
    cudaGetSymbolAddress(&pWs1h, g_Ws1h);
    cudaGetSymbolAddress(&pWs3h, g_Ws3h);
    cudaGetSymbolAddress(&pWs2h, g_Ws2h);
    cudaGetSymbolAddress(&pXh,   g_Xh);

    auto cvt = [&](const float* s, void* d, long long n) {
        int blocks = (int)((n + 2047) / 2048);
        cvt_kernel<<<blocks, 256>>>(s, (__half*)d, (int)n);
    };
    const long long nW  = (long long)NE_ * DIM_ * INTER_;   // 46,137,344
    const long long nWs = (long long)DIM_ * SINTER_;        //  5,767,168
    cvt(x,   pXh,   (long long)T_ * DIM_);
    cvt(W1,  pW1h,  nW);
    cvt(W3,  pW3h,  nW);
    cvt(W2,  pW2h,  nW);
    cvt(Ws1, pWs1h, nWs);
    cvt(Ws3, pWs3h, nWs);
    cvt(Ws2, pWs2h, nWs);

    detect_kernel<<<1, 32>>>(idx);
    build_lists<<<NE_, 256>>>(idx);
    prefix_kernel<<<1, 32>>>();

    // routed up: H = silu(X@W1e) * (X@W3e)
    up_kernel<true ><<<dim3(INTER_  / BN, NPAIR / BM, NE_), 512, upBytes>>>();
    // shared up
    up_kernel<false><<<dim3(SINTER_ / BN, T_    / BM, 1  ), 512, upBytes>>>();
    // routed down: Yb[pair] = w[pair] * (H @ W2e)
    down_kernel<true ><<<dim3(DIM_ / BND, NPAIR / BM, NE_), 512, downBytes>>>(wts);
    // shared down: Z = Hs @ Ws2
    down_kernel<false><<<dim3(DIM_ / BND, T_    / BM, 1  ), 512, downBytes>>>(nullptr);
    reduce_kernel<<<(T_ * DIM_ / 4) / 256, 256>>>(out);
}

// round 10
// speedup vs baseline: 4.5082x; 1.1351x over previous
#include <cuda_runtime.h>
#include <cuda_fp16.h>
#include <mma.h>
#include <cstdint>

using namespace nvcuda;

// ---------------- problem constants ----------------
constexpr int T_      = 2048;
constexpr int DIM_    = 2048;
constexpr int INTER_  = 1408;
constexpr int SINTER_ = 2816;
constexpr int NE_     = 16;
constexpr int TOPK_   = 6;
constexpr int NPAIR   = T_ * TOPK_;      // 12288

// ---------------- tiling ----------------
constexpr int BM     = 128;
constexpr int BN_UP  = 128;   // up: per weight-matrix N tile (128x128 per 8-warp group)
constexpr int BND    = 128;   // down: N tile
constexpr int BK     = 32;    // K per stage (2 mma k-steps of 16)
constexpr int STAGES = 4;
constexpr int BKP    = BK    + 8;  // 40 halves
constexpr int BNPU   = BN_UP + 8;  // 136 halves
constexpr int BNDP   = BND   + 8;  // 136 halves
constexpr int HROWS  = NPAIR + NE_ * BM;

constexpr int UP_PIPE_B   = STAGES * (BM * BKP + 2 * BK * BNPU) * 2;  // 110,592
constexpr int UP_FUSE_B   = 2 * BM * 132 * 4;                         // 135,168
constexpr int UP_SMEM_B   = (UP_PIPE_B > UP_FUSE_B) ? UP_PIPE_B : UP_FUSE_B;
constexpr int DOWN_SMEM_B = STAGES * (BM * BKP + BK * BNDP) * 2;      //  75,776
constexpr int FP_ST       = 132;   // float patch stride

// ---------------- device scratch (static, no allocation) ----------------
__device__ int    g_is64;
__device__ int    g_cnt[NE_];
__device__ int    g_offpad[NE_ + 1];
__device__ int    g_list[NE_ * NPAIR];
__device__ __half g_W1h [(size_t)NE_ * DIM_ * INTER_];
__device__ __half g_W3h [(size_t)NE_ * DIM_ * INTER_];
__device__ __half g_W2h [(size_t)NE_ * INTER_ * DIM_];
__device__ __half g_Ws1h[(size_t)DIM_ * SINTER_];
__device__ __half g_Ws3h[(size_t)DIM_ * SINTER_];
__device__ __half g_Ws2h[(size_t)SINTER_ * DIM_];
__device__ __half g_Xh  [(size_t)T_ * DIM_];
__device__ __half g_Hh  [(size_t)HROWS * INTER_];
__device__ __half g_Hsh [(size_t)T_ * SINTER_];
__device__ float  g_Yb  [(size_t)NPAIR * DIM_];
__device__ float  g_Z   [(size_t)T_ * DIM_];

// ---------------- cp.async helpers ----------------
__device__ __forceinline__ void cpa16(__half* smem, const __half* g) {
    unsigned saddr = (unsigned)__cvta_generic_to_shared(smem);
    asm volatile("cp.async.cg.shared.global [%0], [%1], 16;" :: "r"(saddr), "l"(g));
}
#define CP_COMMIT()  asm volatile("cp.async.commit_group;")
#define CP_WAIT(n)   asm volatile("cp.async.wait_group %0;" :: "n"(n))

// ---------------- fp32 -> fp16 conversion prepass ----------------
__global__ void __launch_bounds__(256, 4) cvt_kernel(const float* __restrict__ s,
                                                     __half* __restrict__ d, int n) {
    int i = (blockIdx.x * 256 + threadIdx.x) * 8;
    if (i >= n) return;
    float4 a = *(const float4*)(s + i);
    float4 b = *(const float4*)(s + i + 4);
    __half2 h0 = __floats2half2_rn(a.x, a.y), h1 = __floats2half2_rn(a.z, a.w);
    __half2 h2 = __floats2half2_rn(b.x, b.y), h3 = __floats2half2_rn(b.z, b.w);
    uint4 o;
    o.x = *reinterpret_cast<unsigned*>(&h0);
    o.y = *reinterpret_cast<unsigned*>(&h1);
    o.z = *reinterpret_cast<unsigned*>(&h2);
    o.w = *reinterpret_cast<unsigned*>(&h3);
    *reinterpret_cast<uint4*>(d + i) = o;
}

// ---------------- dtype probe (int64 vs int32 indices) ----------------
__global__ void detect_kernel(const int* __restrict__ idx32) {
    if (threadIdx.x == 0) {
        int a = 0;
        #pragma unroll 1
        for (int i = 0; i < 128; i++) a |= idx32[2 * i + 1];
        g_is64 = (a == 0) ? 1 : 0;
    }
}

// ---------------- deterministic per-expert pair lists ----------------
__global__ void build_lists(const int* __restrict__ idx32) {
    const int e = blockIdx.x;
    const bool is64 = (g_is64 != 0);
    __shared__ int wsum[8];
    __shared__ int sbase;
    const int tid = threadIdx.x, lane = tid & 31, w = tid >> 5;
    if (tid == 0) sbase = 0;
    __syncthreads();
    for (int st = 0; st < NPAIR; st += 256) {
        int p = st + tid;
        int v = is64 ? idx32[2 * p] : idx32[p];
        bool m = (v == e);
        unsigned bal = __ballot_sync(0xffffffffu, m);
        int within = __popc(bal & ((1u << lane) - 1u));
        if (lane == 0) wsum[w] = __popc(bal);
        __syncthreads();
        int off = sbase;
        for (int i = 0; i < w; i++) off += wsum[i];
        if (m) g_list[e * NPAIR + off + within] = p;
        __syncthreads();
        if (tid == 0) {
            int tot = 0;
            for (int i = 0; i < 8; i++) tot += wsum[i];
            sbase += tot;
        }
        __syncthreads();
    }
    if (tid == 0) g_cnt[e] = sbase;
}

__global__ void prefix_kernel() {
    if (threadIdx.x == 0) {
        int off = 0;
        for (int e = 0; e < NE_; e++) {
            g_offpad[e] = off;
            off += ((g_cnt[e] + BM - 1) / BM) * BM;
        }
        g_offpad[NE_] = off;
    }
}

// ---------------- wmma types (fp16 in, fp32 accum) ----------------
typedef wmma::fragment<wmma::matrix_a, 16, 16, 16, __half, wmma::row_major> FA;
typedef wmma::fragment<wmma::matrix_b, 16, 16, 16, __half, wmma::row_major> FB;
typedef wmma::fragment<wmma::accumulator, 16, 16, 16, float> FC;

// =====================================================================
// up kernel: H = silu(X@W1) * (X@W3).  512 threads, 16 warps.
// Group 0 (warps 0-7): 128x128 of X@W1; group 1: 128x128 of X@W3.
// Warp tile 64x32 (2 warps M x 4 warps N per group).
// =====================================================================
template<bool GATHER>
__global__ void __launch_bounds__(512, 1)
up_kernel()
{
    constexpr int N  = GATHER ? INTER_ : SINTER_;
    constexpr int KT = DIM_ / BK;     // 64
    const int e = blockIdx.z;
    int cnt, hbase;
    if (GATHER) {
        cnt = g_cnt[e];
        if ((int)blockIdx.y * BM >= cnt) return;
        hbase = g_offpad[e] + blockIdx.y * BM;
    } else {
        cnt = T_;
        hbase = blockIdx.y * BM;
    }
    __half* Hout = GATHER ? g_Hh : g_Hsh;
    const __half* B1 = GATHER ? (g_W1h + (size_t)e * DIM_ * N) : g_Ws1h;
    const __half* B3 = GATHER ? (g_W3h + (size_t)e * DIM_ * N) : g_Ws3h;
    const int n0 = blockIdx.x * BN_UP;

    extern __shared__ __half sm[];
    __half* sA  = sm;                                  // [S][BM][BKP]
    __half* sB1 = sm + STAGES * BM * BKP;              // [S][BK][BNPU]
    __half* sB3 = sB1 + STAGES * BK * BNPU;

    const int tid  = threadIdx.x;
    const int warp = tid >> 5;
    const int grp  = warp >> 3;        // 0: W1, 1: W3
    const int wl   = warp & 7;
    const int wm   = wl & 1;           // 2 warps in M (64 rows each)
    const int wn   = wl >> 1;          // 4 warps in N (32 cols each)

    // ---- A copy: one 16B chunk per thread (512 * 8 halves = 128x32)
    const int arow = tid >> 2;
    const int ac8  = (tid & 3) * 8;
    int tok;
    if (GATHER) {
        int row = blockIdx.y * BM + arow;
        tok = (row < cnt) ? (g_list[e * NPAIR + row] / TOPK_) : 0;
    } else {
        tok = blockIdx.y * BM + arow;
    }
    const __half* aptr = g_Xh + (size_t)tok * DIM_ + ac8;

    // ---- B copy: threads 0-255 fill B1, 256-511 fill B3; 2 chunks each
    // matrix tile is 32x128 halves = 512 chunks; chunk = base + 256*i
    const int bmat = tid >> 8;
    const int base = tid & 255;
    const int bcol = (base & 15) * 8;
    const int brow0 = base >> 4;       // rows 0..15 (i=0), +16 (i=1)
    const __half* bsrcM = (bmat ? B3 : B1);
    const __half* bsrc0 = bsrcM + (size_t)brow0 * N + n0 + bcol;
    const __half* bsrc1 = bsrcM + (size_t)(brow0 + 16) * N + n0 + bcol;
    __half* bdst = bmat ? sB3 : sB1;

    auto copy_stage = [&](int kt, int st) {
        const int k0 = kt * BK;
        cpa16(&sA[(st * BM + arow) * BKP + ac8], aptr + k0);
        cpa16(&bdst[(st * BK + brow0) * BNPU + bcol],      bsrc0 + (size_t)k0 * N);
        cpa16(&bdst[(st * BK + brow0 + 16) * BNPU + bcol], bsrc1 + (size_t)k0 * N);
    };

    FC acc[4][2];
    #pragma unroll
    for (int mi = 0; mi < 4; mi++)
        #pragma unroll
        for (int ni = 0; ni < 2; ni++) wmma::fill_fragment(acc[mi][ni], 0.f);

    const __half* sBg = grp ? sB3 : sB1;

    #pragma unroll
    for (int s = 0; s < STAGES - 1; s++) { copy_stage(s, s); CP_COMMIT(); }

    for (int kt = 0; kt < KT; kt++) {
        CP_WAIT(STAGES - 2);
        __syncthreads();
        int nk = kt + STAGES - 1;
        if (nk < KT) copy_stage(nk, nk % STAGES);
        CP_COMMIT();
        const int st = kt % STAGES;
        #pragma unroll
        for (int kk = 0; kk < BK; kk += 16) {
            FA fa[4];
            FB fb[2];
            #pragma unroll
            for (int mi = 0; mi < 4; mi++)
                wmma::load_matrix_sync(fa[mi], &sA[(st * BM + wm * 64 + mi * 16) * BKP + kk], BKP);
            #pragma unroll
            for (int ni = 0; ni < 2; ni++)
                wmma::load_matrix_sync(fb[ni], &sBg[(st * BK + kk) * BNPU + wn * 32 + ni * 16], BNPU);
            #pragma unroll
            for (int mi = 0; mi < 4; mi++)
                #pragma unroll
                for (int ni = 0; ni < 2; ni++)
                    wmma::mma_sync(acc[mi][ni], fa[mi], fb[ni], acc[mi][ni]);
        }
    }

    // ---- epilogue: dump both groups' accs to smem floats, fuse, store fp16 H
    CP_WAIT(0);
    __syncthreads();
    float* sF  = (float*)sm;                  // [2][BM][FP_ST]
    float* sFm = sF + grp * (BM * FP_ST);
    #pragma unroll
    for (int mi = 0; mi < 4; mi++)
        #pragma unroll
        for (int ni = 0; ni < 2; ni++)
            wmma::store_matrix_sync(&sFm[(wm * 64 + mi * 16) * FP_ST + wn * 32 + ni * 16],
                                    acc[mi][ni], FP_ST, wmma::mem_row_major);
    __syncthreads();

    {
        const int row = tid >> 2;
        const int seg = (tid & 3) * 32;
        const float* p1 = &sF[row * FP_ST + seg];
        const float* p3 = p1 + BM * FP_ST;
        __align__(16) __half hbuf[32];
        #pragma unroll
        for (int j = 0; j < 32; j++) {
            float u = p1[j];
            float s = u / (1.f + __expf(-u));
            hbuf[j] = __float2half_rn(s * p3[j]);
        }
        __half* dst = Hout + (size_t)(hbase + row) * N + n0 + seg;
        #pragma unroll
        for (int j = 0; j < 32; j += 8)
            *(uint4*)(dst + j) = *(uint4*)(hbuf + j);
    }
}

// =====================================================================
// down kernel: Y = H @ W2.  256 threads, 8 warps (2Mx4N), warp tile 64x32,
// tile 128x128, 2 CTAs/SM target.
// ROUTED: scatter rows by pair id scaled by routing weight into g_Yb.
// =====================================================================
template<bool ROUTED>
__global__ void __launch_bounds__(256, 2)
down_kernel(const float* __restrict__ wts)
{
    constexpr int K  = ROUTED ? INTER_ : SINTER_;
    constexpr int KT = K / BK;        // 44 or 88
    const int e = blockIdx.z;
    int cnt, abase;
    if (ROUTED) {
        cnt = g_cnt[e];
        if ((int)blockIdx.y * BM >= cnt) return;
        abase = g_offpad[e] + blockIdx.y * BM;
    } else {
        cnt = T_;
        abase = blockIdx.y * BM;
    }
    const __half* Hin = ROUTED ? g_Hh : g_Hsh;
    const __half* Bh  = ROUTED ? (g_W2h + (size_t)e * K * DIM_) : g_Ws2h;
    const int n0 = blockIdx.x * BND;

    extern __shared__ __half sm[];
    __half* sA = sm;                                // [S][BM][BKP]
    __half* sB = sm + STAGES * BM * BKP;            // [S][BK][BNDP]

    const int tid  = threadIdx.x;
    const int warp = tid >> 5;
    const int wm   = warp & 1;       // 2 warps in M (64 rows)
    const int wn   = warp >> 1;      // 4 warps in N (32 cols)

    // A copy: 2 chunks per thread; chunk = tid + 256*i
    const int arow0 = tid >> 2;            // rows 0..63 (i=0), +64 (i=1)
    const int ac8   = (tid & 3) * 8;
    const __half* aptr0 = Hin + (size_t)(abase + arow0) * K + ac8;
    const __half* aptr1 = Hin + (size_t)(abase + arow0 + 64) * K + ac8;

    // B copy: 2 chunks per thread
    const int bcol  = (tid & 15) * 8;
    const int brow0 = tid >> 4;            // rows 0..15 (i=0), +16 (i=1)
    const __half* bsrc0 = Bh + (size_t)brow0 * DIM_ + n0 + bcol;
    const __half* bsrc1 = Bh + (size_t)(brow0 + 16) * DIM_ + n0 + bcol;

    auto copy_stage = [&](int kt, int st) {
        const int k0 = kt * BK;
        cpa16(&sA[(st * BM + arow0) * BKP + ac8],      aptr0 + k0);
        cpa16(&sA[(st * BM + arow0 + 64) * BKP + ac8], aptr1 + k0);
        cpa16(&sB[(st * BK + brow0) * BNDP + bcol],      bsrc0 + (size_t)k0 * DIM_);
        cpa16(&sB[(st * BK + brow0 + 16) * BNDP + bcol], bsrc1 + (size_t)k0 * DIM_);
    };

    FC acc[4][2];
    #pragma unroll
    for (int mi = 0; mi < 4; mi++)
        #pragma unroll
        for (int ni = 0; ni < 2; ni++) wmma::fill_fragment(acc[mi][ni], 0.f);

    #pragma unroll
    for (int s = 0; s < STAGES - 1; s++) { copy_stage(s, s); CP_COMMIT(); }

    for (int kt = 0; kt < KT; kt++) {
        CP_WAIT(STAGES - 2);
        __syncthreads();
        int nk = kt + STAGES - 1;
        if (nk < KT) copy_stage(nk, nk % STAGES);
        CP_COMMIT();
        const int st = kt % STAGES;
        #pragma unroll
        for (int kk = 0; kk < BK; kk += 16) {
            FA fa[4];
            FB fb[2];
            #pragma unroll
            for (int mi = 0; mi < 4; mi++)
                wmma::load_matrix_sync(fa[mi], &sA[(st * BM + wm * 64 + mi * 16) * BKP + kk], BKP);
            #pragma unroll
            for (int ni = 0; ni < 2; ni++)
                wmma::load_matrix_sync(fb[ni], &sB[(st * BK + kk) * BNDP + wn * 32 + ni * 16], BNDP);
            #pragma unroll
            for (int mi = 0; mi < 4; mi++)
                #pragma unroll
                for (int ni = 0; ni < 2; ni++)
                    wmma::mma_sync(acc[mi][ni], fa[mi], fb[ni], acc[mi][ni]);
        }
    }

    // ---- epilogue: dump to smem floats, then coalesced scatter/store
    CP_WAIT(0);
    __syncthreads();
    float* sF = (float*)sm;                   // [BM][FP_ST]  (67.6KB <= 75.7KB)
    #pragma unroll
    for (int mi = 0; mi < 4; mi++)
        #pragma unroll
        for (int ni = 0; ni < 2; ni++)
            wmma::store_matrix_sync(&sF[(wm * 64 + mi * 16) * FP_ST + wn * 32 + ni * 16],
                                    acc[mi][ni], FP_ST, wmma::mem_row_major);
    __syncthreads();

    {
        const int row = tid >> 1;
        const int seg = (tid & 1) * 64;
        const float* src = &sF[row * FP_ST + seg];
        if (ROUTED) {
            int gslot = blockIdx.y * BM + row;
            if (gslot < cnt) {
                int p = g_list[e * NPAIR + gslot];
                float w = wts[p];
                float* dst = g_Yb + (size_t)p * DIM_ + n0 + seg;
                #pragma unroll
                for (int j = 0; j < 64; j += 4) {
                    float4 v = *(const float4*)(src + j);
                    v.x *= w; v.y *= w; v.z *= w; v.w *= w;
                    *(float4*)(dst + j) = v;
                }
            }
        } else {
            float* dst = g_Z + (size_t)(abase + row) * DIM_ + n0 + seg;
            #pragma unroll
            for (int j = 0; j < 64; j += 4)
                *(float4*)(dst + j) = *(const float4*)(src + j);
        }
    }
}

// ---------------- final reduction: out = sum_k Yb[t,k] + Z ----------------
__global__ void __launch_bounds__(256, 1) reduce_kernel(float* __restrict__ out) {
    int i = blockIdx.x * 256 + threadIdx.x;
    const int row4 = DIM_ / 4;
    int t  = i / row4;
    int c4 = i % row4;
    float4 a = ((const float4*)g_Z)[i];
    #pragma unroll
    for (int k = 0; k < TOPK_; k++) {
        const float4 v = *(const float4*)(g_Yb + (size_t)(t * TOPK_ + k) * DIM_ + c4 * 4);
        a.x += v.x; a.y += v.y; a.z += v.z; a.w += v.w;
    }
    ((float4*)out)[i] = a;
}

// ---------------- launch ----------------
extern "C" void kernel_launch(void* const* d_in, const int* in_sizes, int n_in,
                              void* d_out, int out_size) {
    const float* x   = (const float*)d_in[0];
    const float* wts = (const float*)d_in[1];
    const int*   idx = (const int*)  d_in[2];
    const float* W1  = (const float*)d_in[3];
    const float* W3  = (const float*)d_in[4];
    const float* W2  = (const float*)d_in[5];
    const float* Ws1 = (const float*)d_in[6];
    const float* Ws3 = (const float*)d_in[7];
    const float* Ws2 = (const float*)d_in[8];
    float* out = (float*)d_out;

    cudaFuncSetAttribute(up_kernel<true>,    cudaFuncAttributeMaxDynamicSharedMemorySize, UP_SMEM_B);
    cudaFuncSetAttribute(up_kernel<false>,   cudaFuncAttributeMaxDynamicSharedMemorySize, UP_SMEM_B);
    cudaFuncSetAttribute(down_kernel<true>,  cudaFuncAttributeMaxDynamicSharedMemorySize, DOWN_SMEM_B);
    cudaFuncSetAttribute(down_kernel<false>, cudaFuncAttributeMaxDynamicSharedMemorySize, DOWN_SMEM_B);

    // fp16 scratch addresses (host query of device symbols; no allocation)
    void *pW1h, *pW3h, *pW2h, *pWs1h, *pWs3h, *pWs2h, *pXh;
    cudaGetSymbolAddress(&pW1h,  g_W1h);
    cudaGetSymbolAddress(&pW3h,  g_W3h);
    cudaGetSymbolAddress(&pW2h,  g_W2h);
    cudaGetSymbolAddress(&pWs1h, g_Ws1h);
    cudaGetSymbolAddress(&pWs3h, g_Ws3h);
    cudaGetSymbolAddress(&pWs2h, g_Ws2h);
    cudaGetSymbolAddress(&pXh,   g_Xh);

    auto cvt = [&](const float* s, void* d, long long n) {
        int blocks = (int)((n + 2047) / 2048);
        cvt_kernel<<<blocks, 256>>>(s, (__half*)d, (int)n);
    };
    const long long nW  = (long long)NE_ * DIM_ * INTER_;   // 46,137,344
    const long long nWs = (long long)DIM_ * SINTER_;        //  5,767,168
    cvt(x,   pXh,   (long long)T_ * DIM_);
    cvt(W1,  pW1h,  nW);
    cvt(W3,  pW3h,  nW);
    cvt(W2,  pW2h,  nW);
    cvt(Ws1, pWs1h, nWs);
    cvt(Ws3, pWs3h, nWs);
    cvt(Ws2, pWs2h, nWs);

    detect_kernel<<<1, 32>>>(idx);
    build_lists<<<NE_, 256>>>(idx);
    prefix_kernel<<<1, 32>>>();

    // routed up: H = silu(X@W1e) * (X@W3e)
    up_kernel<true ><<<dim3(INTER_  / BN_UP, NPAIR / BM, NE_), 512, UP_SMEM_B>>>();
    // shared up
    up_kernel<false><<<dim3(SINTER_ / BN_UP, T_    / BM, 1  ), 512, UP_SMEM_B>>>();
    // routed down: Yb[pair] = w[pair] * (H @ W2e)
    down_kernel<true ><<<dim3(DIM_ / BND, NPAIR / BM, NE_), 256, DOWN_SMEM_B>>>(wts);
    // shared down: Z = Hs @ Ws2
    down_kernel<false><<<dim3(DIM_ / BND, T_    / BM, 1  ), 256, DOWN_SMEM_B>>>(nullptr);
    reduce_kernel<<<(T_ * DIM_ / 4) / 256, 256>>>(out);
}

// round 11
// speedup vs baseline: 4.7607x; 1.0560x over previous
#include <cuda_runtime.h>
#include <cuda_fp16.h>
#include <mma.h>
#include <cstdint>

using namespace nvcuda;

// ---------------- problem constants ----------------
constexpr int T_      = 2048;
constexpr int DIM_    = 2048;
constexpr int INTER_  = 1408;
constexpr int SINTER_ = 2816;
constexpr int NE_     = 16;
constexpr int TOPK_   = 6;
constexpr int NPAIR   = T_ * TOPK_;      // 12288

// ---------------- tiling ----------------
constexpr int BM     = 128;
constexpr int BN_UP  = 128;   // up: per weight-matrix N tile
constexpr int BND    = 128;   // down: N tile
constexpr int BK     = 32;    // K per stage (2 mma k-steps of 16)
constexpr int STAGES = 4;
constexpr int BKP    = BK    + 8;  // 40 halves
constexpr int BNPU   = BN_UP + 8;  // 136 halves
constexpr int BNDP   = BND   + 8;  // 136 halves
constexpr int HROWS  = NPAIR + NE_ * BM;

constexpr int UP_PIPE_B   = STAGES * (BM * BKP + 2 * BK * BNPU) * 2;  // 110,592
constexpr int UP_FUSE_B   = 2 * BM * 132 * 4;                         // 135,168
constexpr int UP_SMEM_B   = (UP_PIPE_B > UP_FUSE_B) ? UP_PIPE_B : UP_FUSE_B;
constexpr int DOWN_SMEM_B = STAGES * (BM * BKP + BK * BNDP) * 2;      //  75,776
constexpr int FP_ST       = 132;   // float patch stride

// ---------------- device scratch (static, no allocation) ----------------
__device__ int    g_is64;
__device__ int    g_cnt[NE_];
__device__ int    g_offpad[NE_ + 1];
__device__ int    g_list[NE_ * NPAIR];
__device__ __half g_W1h [(size_t)NE_ * DIM_ * INTER_];
__device__ __half g_W3h [(size_t)NE_ * DIM_ * INTER_];
__device__ __half g_W2h [(size_t)NE_ * INTER_ * DIM_];
__device__ __half g_Ws1h[(size_t)DIM_ * SINTER_];
__device__ __half g_Ws3h[(size_t)DIM_ * SINTER_];
__device__ __half g_Ws2h[(size_t)SINTER_ * DIM_];
__device__ __half g_Xh  [(size_t)T_ * DIM_];
__device__ __half g_Hh  [(size_t)HROWS * INTER_];
__device__ __half g_Hsh [(size_t)T_ * SINTER_];
__device__ float  g_Yb  [(size_t)NPAIR * DIM_];
__device__ float  g_Z   [(size_t)T_ * DIM_];

// ---------------- cp.async helpers ----------------
__device__ __forceinline__ void cpa16(__half* smem, const __half* g) {
    unsigned saddr = (unsigned)__cvta_generic_to_shared(smem);
    asm volatile("cp.async.cg.shared.global [%0], [%1], 16;" :: "r"(saddr), "l"(g));
}
#define CP_COMMIT()  asm volatile("cp.async.commit_group;")
#define CP_WAIT(n)   asm volatile("cp.async.wait_group %0;" :: "n"(n))

// ---------------- fp32 -> fp16 conversion prepass ----------------
__global__ void __launch_bounds__(256, 4) cvt_kernel(const float* __restrict__ s,
                                                     __half* __restrict__ d, int n) {
    int i = (blockIdx.x * 256 + threadIdx.x) * 8;
    if (i >= n) return;
    float4 a = *(const float4*)(s + i);
    float4 b = *(const float4*)(s + i + 4);
    __half2 h0 = __floats2half2_rn(a.x, a.y), h1 = __floats2half2_rn(a.z, a.w);
    __half2 h2 = __floats2half2_rn(b.x, b.y), h3 = __floats2half2_rn(b.z, b.w);
    uint4 o;
    o.x = *reinterpret_cast<unsigned*>(&h0);
    o.y = *reinterpret_cast<unsigned*>(&h1);
    o.z = *reinterpret_cast<unsigned*>(&h2);
    o.w = *reinterpret_cast<unsigned*>(&h3);
    *reinterpret_cast<uint4*>(d + i) = o;
}

// ---------------- dtype probe (int64 vs int32 indices) ----------------
__global__ void detect_kernel(const int* __restrict__ idx32) {
    if (threadIdx.x == 0) {
        int a = 0;
        #pragma unroll 1
        for (int i = 0; i < 128; i++) a |= idx32[2 * i + 1];
        g_is64 = (a == 0) ? 1 : 0;
    }
}

// ---------------- deterministic per-expert pair lists ----------------
__global__ void build_lists(const int* __restrict__ idx32) {
    const int e = blockIdx.x;
    const bool is64 = (g_is64 != 0);
    __shared__ int wsum[8];
    __shared__ int sbase;
    const int tid = threadIdx.x, lane = tid & 31, w = tid >> 5;
    if (tid == 0) sbase = 0;
    __syncthreads();
    for (int st = 0; st < NPAIR; st += 256) {
        int p = st + tid;
        int v = is64 ? idx32[2 * p] : idx32[p];
        bool m = (v == e);
        unsigned bal = __ballot_sync(0xffffffffu, m);
        int within = __popc(bal & ((1u << lane) - 1u));
        if (lane == 0) wsum[w] = __popc(bal);
        __syncthreads();
        int off = sbase;
        for (int i = 0; i < w; i++) off += wsum[i];
        if (m) g_list[e * NPAIR + off + within] = p;
        __syncthreads();
        if (tid == 0) {
            int tot = 0;
            for (int i = 0; i < 8; i++) tot += wsum[i];
            sbase += tot;
        }
        __syncthreads();
    }
    if (tid == 0) g_cnt[e] = sbase;
}

__global__ void prefix_kernel() {
    if (threadIdx.x == 0) {
        int off = 0;
        for (int e = 0; e < NE_; e++) {
            g_offpad[e] = off;
            off += ((g_cnt[e] + BM - 1) / BM) * BM;
        }
        g_offpad[NE_] = off;
    }
}

// ---------------- wmma types (fp16 in, fp32 accum) ----------------
typedef wmma::fragment<wmma::matrix_a, 16, 16, 16, __half, wmma::row_major> FA;
typedef wmma::fragment<wmma::matrix_b, 16, 16, 16, __half, wmma::row_major> FB;
typedef wmma::fragment<wmma::accumulator, 16, 16, 16, float> FC;

// =====================================================================
// up kernel: H = silu(X@W1) * (X@W3).  256 threads, 8 warps.
// Group 0 (warps 0-3): 128x128 of X@W1; group 1 (warps 4-7): X@W3.
// Warp tile 64x64 (2x2 warps per group), acc 4x4.
// =====================================================================
template<bool GATHER>
__global__ void __launch_bounds__(256, 1)
up_kernel()
{
    constexpr int N  = GATHER ? INTER_ : SINTER_;
    constexpr int KT = DIM_ / BK;     // 64
    const int e = blockIdx.z;
    int cnt, hbase;
    if (GATHER) {
        cnt = g_cnt[e];
        if ((int)blockIdx.y * BM >= cnt) return;
        hbase = g_offpad[e] + blockIdx.y * BM;
    } else {
        cnt = T_;
        hbase = blockIdx.y * BM;
    }
    __half* Hout = GATHER ? g_Hh : g_Hsh;
    const __half* B1 = GATHER ? (g_W1h + (size_t)e * DIM_ * N) : g_Ws1h;
    const __half* B3 = GATHER ? (g_W3h + (size_t)e * DIM_ * N) : g_Ws3h;
    const int n0 = blockIdx.x * BN_UP;

    extern __shared__ __half sm[];
    __half* sA  = sm;                                  // [S][BM][BKP]
    __half* sB1 = sm + STAGES * BM * BKP;              // [S][BK][BNPU]
    __half* sB3 = sB1 + STAGES * BK * BNPU;

    const int tid  = threadIdx.x;
    const int warp = tid >> 5;
    const int grp  = warp >> 2;        // 0: W1, 1: W3
    const int wl   = warp & 3;
    const int wm   = wl & 1;           // 2 warps in M (64 rows each)
    const int wn   = wl >> 1;          // 2 warps in N (64 cols each)

    // ---- A copy: 128x32 halves = 512 chunks, 2 per thread
    const int arow0 = tid >> 1;                 // +64 for second chunk's... no:
    // chunk id = tid + 256*i -> row = id>>2, col8 = (id&3)*8
    int tokA[2];
    #pragma unroll
    for (int i = 0; i < 2; i++) {
        int id  = tid + 256 * i;
        int row = blockIdx.y * BM + (id >> 2);
        if (GATHER) tokA[i] = (row < cnt + blockIdx.y * 0 && (id >> 2) + blockIdx.y * BM < cnt)
                              ? g_list[e * NPAIR + blockIdx.y * BM + (id >> 2)] / TOPK_ : 0;
        else        tokA[i] = row;
    }
    // simplify: recompute cleanly
    const __half* aptr[2];
    uint32_t asoff[2];
    #pragma unroll
    for (int i = 0; i < 2; i++) {
        int id  = tid + 256 * i;
        int r   = id >> 2;
        int c8  = (id & 3) * 8;
        int row = blockIdx.y * BM + r;
        int tok;
        if (GATHER) tok = (row < cnt) ? (g_list[e * NPAIR + row] / TOPK_) : 0;
        else        tok = row;
        aptr[i]  = g_Xh + (size_t)tok * DIM_ + c8;
        asoff[i] = r * BKP + c8;
    }

    // ---- B copy: per matrix 32x128 halves = 512 chunks; threads 0-127 -> B1,
    // 128-255 -> B3, 4 chunks each: id = (tid&127) + 128*i
    const int bmat = tid >> 7;
    const __half* bsrcM = bmat ? B3 : B1;
    __half* bdst = bmat ? sB3 : sB1;
    const __half* bptr[4];
    uint32_t bsoff[4];
    #pragma unroll
    for (int i = 0; i < 4; i++) {
        int id = (tid & 127) + 128 * i;
        int r  = id >> 4;
        int c8 = (id & 15) * 8;
        bptr[i]  = bsrcM + (size_t)r * N + n0 + c8;
        bsoff[i] = r * BNPU + c8;
    }

    auto copy_stage = [&](int kt, int st) {
        const int k0 = kt * BK;
        #pragma unroll
        for (int i = 0; i < 2; i++)
            cpa16(&sA[st * BM * BKP + asoff[i]], aptr[i] + k0);
        #pragma unroll
        for (int i = 0; i < 4; i++)
            cpa16(&bdst[st * BK * BNPU + bsoff[i]], bptr[i] + (size_t)k0 * N);
    };

    FC acc[4][4];
    #pragma unroll
    for (int mi = 0; mi < 4; mi++)
        #pragma unroll
        for (int ni = 0; ni < 4; ni++) wmma::fill_fragment(acc[mi][ni], 0.f);

    const __half* sBg = grp ? sB3 : sB1;

    #pragma unroll
    for (int s = 0; s < STAGES - 1; s++) { copy_stage(s, s); CP_COMMIT(); }

    for (int kt = 0; kt < KT; kt++) {
        CP_WAIT(STAGES - 2);
        __syncthreads();
        int nk = kt + STAGES - 1;
        if (nk < KT) copy_stage(nk, nk % STAGES);
        CP_COMMIT();
        const int st = kt % STAGES;
        #pragma unroll
        for (int kk = 0; kk < BK; kk += 16) {
            FA fa[4];
            FB fb[4];
            #pragma unroll
            for (int mi = 0; mi < 4; mi++)
                wmma::load_matrix_sync(fa[mi], &sA[(st * BM + wm * 64 + mi * 16) * BKP + kk], BKP);
            #pragma unroll
            for (int ni = 0; ni < 4; ni++)
                wmma::load_matrix_sync(fb[ni], &sBg[(st * BK + kk) * BNPU + wn * 64 + ni * 16], BNPU);
            #pragma unroll
            for (int mi = 0; mi < 4; mi++)
                #pragma unroll
                for (int ni = 0; ni < 4; ni++)
                    wmma::mma_sync(acc[mi][ni], fa[mi], fb[ni], acc[mi][ni]);
        }
    }

    // ---- epilogue: dump both groups' accs to smem floats, fuse, store fp16 H
    CP_WAIT(0);
    __syncthreads();
    float* sF  = (float*)sm;                  // [2][BM][FP_ST]
    float* sFm = sF + grp * (BM * FP_ST);
    #pragma unroll
    for (int mi = 0; mi < 4; mi++)
        #pragma unroll
        for (int ni = 0; ni < 4; ni++)
            wmma::store_matrix_sync(&sFm[(wm * 64 + mi * 16) * FP_ST + wn * 64 + ni * 16],
                                    acc[mi][ni], FP_ST, wmma::mem_row_major);
    __syncthreads();

    {
        const int row = tid >> 1;
        const int seg = (tid & 1) * 64;
        const float* p1 = &sF[row * FP_ST + seg];
        const float* p3 = p1 + BM * FP_ST;
        __half* dst = Hout + (size_t)(hbase + row) * N + n0 + seg;
        #pragma unroll
        for (int c = 0; c < 64; c += 16) {
            __align__(16) __half hbuf[16];
            #pragma unroll
            for (int j = 0; j < 16; j++) {
                float u = p1[c + j];
                float s = u / (1.f + __expf(-u));
                hbuf[j] = __float2half_rn(s * p3[c + j]);
            }
            *(uint4*)(dst + c)     = *(uint4*)(hbuf);
            *(uint4*)(dst + c + 8) = *(uint4*)(hbuf + 8);
        }
    }
}

// =====================================================================
// down kernel: Y = H @ W2.  128 threads, 4 warps (2x2), warp tile 64x64,
// tile 128x128, 2 CTAs/SM.
// ROUTED: scatter rows by pair id scaled by routing weight into g_Yb.
// =====================================================================
template<bool ROUTED>
__global__ void __launch_bounds__(128, 2)
down_kernel(const float* __restrict__ wts)
{
    constexpr int K  = ROUTED ? INTER_ : SINTER_;
    constexpr int KT = K / BK;        // 44 or 88
    const int e = blockIdx.z;
    int cnt, abase;
    if (ROUTED) {
        cnt = g_cnt[e];
        if ((int)blockIdx.y * BM >= cnt) return;
        abase = g_offpad[e] + blockIdx.y * BM;
    } else {
        cnt = T_;
        abase = blockIdx.y * BM;
    }
    const __half* Hin = ROUTED ? g_Hh : g_Hsh;
    const __half* Bh  = ROUTED ? (g_W2h + (size_t)e * K * DIM_) : g_Ws2h;
    const int n0 = blockIdx.x * BND;

    extern __shared__ __half sm[];
    __half* sA = sm;                                // [S][BM][BKP]
    __half* sB = sm + STAGES * BM * BKP;            // [S][BK][BNDP]

    const int tid  = threadIdx.x;
    const int warp = tid >> 5;
    const int wm   = warp & 1;       // 2 warps in M (64 rows)
    const int wn   = warp >> 1;      // 2 warps in N (64 cols)

    // A copy: 128x32 halves = 512 chunks, 4 per thread: id = tid + 128*i
    const __half* aptr[4];
    uint32_t asoff[4];
    #pragma unroll
    for (int i = 0; i < 4; i++) {
        int id = tid + 128 * i;
        int r  = id >> 2;
        int c8 = (id & 3) * 8;
        aptr[i]  = Hin + (size_t)(abase + r) * K + c8;
        asoff[i] = r * BKP + c8;
    }
    // B copy: 32x128 halves = 512 chunks, 4 per thread
    const __half* bptr[4];
    uint32_t bsoff[4];
    #pragma unroll
    for (int i = 0; i < 4; i++) {
        int id = tid + 128 * i;
        int r  = id >> 4;
        int c8 = (id & 15) * 8;
        bptr[i]  = Bh + (size_t)r * DIM_ + n0 + c8;
        bsoff[i] = r * BNDP + c8;
    }

    auto copy_stage = [&](int kt, int st) {
        const int k0 = kt * BK;
        #pragma unroll
        for (int i = 0; i < 4; i++)
            cpa16(&sA[st * BM * BKP + asoff[i]], aptr[i] + k0);
        #pragma unroll
        for (int i = 0; i < 4; i++)
            cpa16(&sB[st * BK * BNDP + bsoff[i]], bptr[i] + (size_t)k0 * DIM_);
    };

    FC acc[4][4];
    #pragma unroll
    for (int mi = 0; mi < 4; mi++)
        #pragma unroll
        for (int ni = 0; ni < 4; ni++) wmma::fill_fragment(acc[mi][ni], 0.f);

    #pragma unroll
    for (int s = 0; s < STAGES - 1; s++) { copy_stage(s, s); CP_COMMIT(); }

    for (int kt = 0; kt < KT; kt++) {
        CP_WAIT(STAGES - 2);
        __syncthreads();
        int nk = kt + STAGES - 1;
        if (nk < KT) copy_stage(nk, nk % STAGES);
        CP_COMMIT();
        const int st = kt % STAGES;
        #pragma unroll
        for (int kk = 0; kk < BK; kk += 16) {
            FA fa[4];
            FB fb[4];
            #pragma unroll
            for (int mi = 0; mi < 4; mi++)
                wmma::load_matrix_sync(fa[mi], &sA[(st * BM + wm * 64 + mi * 16) * BKP + kk], BKP);
            #pragma unroll
            for (int ni = 0; ni < 4; ni++)
                wmma::load_matrix_sync(fb[ni], &sB[(st * BK + kk) * BNDP + wn * 64 + ni * 16], BNDP);
            #pragma unroll
            for (int mi = 0; mi < 4; mi++)
                #pragma unroll
                for (int ni = 0; ni < 4; ni++)
                    wmma::mma_sync(acc[mi][ni], fa[mi], fb[ni], acc[mi][ni]);
        }
    }

    // ---- epilogue: dump to smem floats, then scatter/store
    CP_WAIT(0);
    __syncthreads();
    float* sF = (float*)sm;                   // [BM][FP_ST]  (67.6KB <= 75.7KB)
    #pragma unroll
    for (int mi = 0; mi < 4; mi++)
        #pragma unroll
        for (int ni = 0; ni < 4; ni++)
            wmma::store_matrix_sync(&sF[(wm * 64 + mi * 16) * FP_ST + wn * 64 + ni * 16],
                                    acc[mi][ni], FP_ST, wmma::mem_row_major);
    __syncthreads();

    {
        const int row = tid;                  // one row per thread
        const float* src = &sF[row * FP_ST];
        if (ROUTED) {
            int gslot = blockIdx.y * BM + row;
            if (gslot < cnt) {
                int p = g_list[e * NPAIR + gslot];
                float w = wts[p];
                float* dst = g_Yb + (size_t)p * DIM_ + n0;
                #pragma unroll
                for (int j = 0; j < 128; j += 4) {
                    float4 v = *(const float4*)(src + j);
                    v.x *= w; v.y *= w; v.z *= w; v.w *= w;
                    *(float4*)(dst + j) = v;
                }
            }
        } else {
            float* dst = g_Z + (size_t)(abase + row) * DIM_ + n0;
            #pragma unroll
            for (int j = 0; j < 128; j += 4)
                *(float4*)(dst + j) = *(const float4*)(src + j);
        }
    }
}

// ---------------- final reduction: out = sum_k Yb[t,k] + Z ----------------
__global__ void __launch_bounds__(256, 1) reduce_kernel(float* __restrict__ out) {
    int i = blockIdx.x * 256 + threadIdx.x;
    const int row4 = DIM_ / 4;
    int t  = i / row4;
    int c4 = i % row4;
    float4 a = ((const float4*)g_Z)[i];
    #pragma unroll
    for (int k = 0; k < TOPK_; k++) {
        const float4 v = *(const float4*)(g_Yb + (size_t)(t * TOPK_ + k) * DIM_ + c4 * 4);
        a.x += v.x; a.y += v.y; a.z += v.z; a.w += v.w;
    }
    ((float4*)out)[i] = a;
}

// ---------------- launch ----------------
extern "C" void kernel_launch(void* const* d_in, const int* in_sizes, int n_in,
                              void* d_out, int out_size) {
    const float* x   = (const float*)d_in[0];
    const float* wts = (const float*)d_in[1];
    const int*   idx = (const int*)  d_in[2];
    const float* W1  = (const float*)d_in[3];
    const float* W3  = (const float*)d_in[4];
    const float* W2  = (const float*)d_in[5];
    const float* Ws1 = (const float*)d_in[6];
    const float* Ws3 = (const float*)d_in[7];
    const float* Ws2 = (const float*)d_in[8];
    float* out = (float*)d_out;

    cudaFuncSetAttribute(up_kernel<true>,    cudaFuncAttributeMaxDynamicSharedMemorySize, UP_SMEM_B);
    cudaFuncSetAttribute(up_kernel<false>,   cudaFuncAttributeMaxDynamicSharedMemorySize, UP_SMEM_B);
    cudaFuncSetAttribute(down_kernel<true>,  cudaFuncAttributeMaxDynamicSharedMemorySize, DOWN_SMEM_B);
    cudaFuncSetAttribute(down_kernel<false>, cudaFuncAttributeMaxDynamicSharedMemorySize, DOWN_SMEM_B);

    // fp16 scratch addresses (host query of device symbols; no allocation)
    void *pW1h, *pW3h, *pW2h, *pWs1h, *pWs3h, *pWs2h, *pXh;
    cudaGetSymbolAddress(&pW1h,  g_W1h);
    cudaGetSymbolAddress(&pW3h,  g_W3h);
    cudaGetSymbolAddress(&pW2h,  g_W2h);
    cudaGetSymbolAddress(&pWs1h, g_Ws1h);
    cudaGetSymbolAddress(&pWs3h, g_Ws3h);
    cudaGetSymbolAddress(&pWs2h, g_Ws2h);
    cudaGetSymbolAddress(&pXh,   g_Xh);

    auto cvt = [&](const float* s, void* d, long long n) {
        int blocks = (int)((n + 2047) / 2048);
        cvt_kernel<<<blocks, 256>>>(s, (__half*)d, (int)n);
    };
    const long long nW  = (long long)NE_ * DIM_ * INTER_;   // 46,137,344
    const long long nWs = (long long)DIM_ * SINTER_;        //  5,767,168
    cvt(x,   pXh,   (long long)T_ * DIM_);
    cvt(W1,  pW1h,  nW);
    cvt(W3,  pW3h,  nW);
    cvt(W2,  pW2h,  nW);
    cvt(Ws1, pWs1h, nWs);
    cvt(Ws3, pWs3h, nWs);
    cvt(Ws2, pWs2h, nWs);

    detect_kernel<<<1, 32>>>(idx);
    build_lists<<<NE_, 256>>>(idx);
    prefix_kernel<<<1, 32>>>();

    // routed up: H = silu(X@W1e) * (X@W3e)
    up_kernel<true ><<<dim3(INTER_  / BN_UP, NPAIR / BM, NE_), 256, UP_SMEM_B>>>();
    // shared up
    up_kernel<false><<<dim3(SINTER_ / BN_UP, T_    / BM, 1  ), 256, UP_SMEM_B>>>();
    // routed down: Yb[pair] = w[pair] * (H @ W2e)
    down_kernel<true ><<<dim3(DIM_ / BND, NPAIR / BM, NE_), 128, DOWN_SMEM_B>>>(wts);
    // shared down: Z = Hs @ Ws2
    down_kernel<false><<<dim3(DIM_ / BND, T_    / BM, 1  ), 128, DOWN_SMEM_B>>>(nullptr);
    reduce_kernel<<<(T_ * DIM_ / 4) / 256, 256>>>(out);
}

// round 12
// speedup vs baseline: 4.8996x; 1.0292x over previous
#include <cuda_runtime.h>
#include <cuda_fp16.h>
#include <mma.h>
#include <cstdint>

using namespace nvcuda;

// ---------------- problem constants ----------------
constexpr int T_      = 2048;
constexpr int DIM_    = 2048;
constexpr int INTER_  = 1408;
constexpr int SINTER_ = 2816;          // == 2 * INTER_
constexpr int NE_     = 16;
constexpr int NE2     = 18;            // 16 routed + 2 shared pseudo-experts
constexpr int TOPK_   = 6;
constexpr int NSLOT   = 8;             // 6 routed + 2 shared
constexpr int NPAIR   = T_ * TOPK_;    // 12288

// ---------------- tiling ----------------
constexpr int BM     = 128;
constexpr int BN_UP  = 128;
constexpr int BND    = 128;
constexpr int BK     = 32;
constexpr int STAGES = 4;
constexpr int BKP    = BK    + 8;
constexpr int BNPU   = BN_UP + 8;
constexpr int BNDP   = BND   + 8;
constexpr int HROWS  = NPAIR + NE_ * BM + 2 * T_;   // 18,432 padded rows

constexpr int UP_PIPE_B   = STAGES * (BM * BKP + 2 * BK * BNPU) * 2;  // 110,592
constexpr int UP_FUSE_B   = 2 * BM * 132 * 4;                         // 135,168
constexpr int UP_SMEM_B   = (UP_PIPE_B > UP_FUSE_B) ? UP_PIPE_B : UP_FUSE_B;
constexpr int DOWN_SMEM_B = STAGES * (BM * BKP + BK * BNDP) * 2;      //  75,776
constexpr int FP_ST       = 132;

// ---------------- device scratch (static, no allocation) ----------------
__device__ int    g_is64;
__device__ int    g_cnt[NE2];
__device__ int    g_offpad[NE2 + 1];
__device__ int    g_list[NE_ * NPAIR];
__device__ __half g_W1h [(size_t)NE_ * DIM_ * INTER_];
__device__ __half g_W3h [(size_t)NE_ * DIM_ * INTER_];
__device__ __half g_W2h [(size_t)NE_ * INTER_ * DIM_];
__device__ __half g_Ws1h[(size_t)DIM_ * SINTER_];
__device__ __half g_Ws3h[(size_t)DIM_ * SINTER_];
__device__ __half g_Ws2h[(size_t)SINTER_ * DIM_];
__device__ __half g_Xh  [(size_t)T_ * DIM_];
__device__ __half g_Hh  [(size_t)HROWS * INTER_];
__device__ float  g_Yb  [(size_t)T_ * NSLOT * DIM_];

// ---------------- cp.async helpers ----------------
__device__ __forceinline__ void cpa16(__half* smem, const __half* g) {
    unsigned saddr = (unsigned)__cvta_generic_to_shared(smem);
    asm volatile("cp.async.cg.shared.global [%0], [%1], 16;" :: "r"(saddr), "l"(g));
}
#define CP_COMMIT()  asm volatile("cp.async.commit_group;")
#define CP_WAIT(n)   asm volatile("cp.async.wait_group %0;" :: "n"(n))

// ---------------- fp32 -> fp16 conversion prepass ----------------
__global__ void __launch_bounds__(256, 4) cvt_kernel(const float* __restrict__ s,
                                                     __half* __restrict__ d, int n) {
    int i = (blockIdx.x * 256 + threadIdx.x) * 8;
    if (i >= n) return;
    float4 a = *(const float4*)(s + i);
    float4 b = *(const float4*)(s + i + 4);
    __half2 h0 = __floats2half2_rn(a.x, a.y), h1 = __floats2half2_rn(a.z, a.w);
    __half2 h2 = __floats2half2_rn(b.x, b.y), h3 = __floats2half2_rn(b.z, b.w);
    uint4 o;
    o.x = *reinterpret_cast<unsigned*>(&h0);
    o.y = *reinterpret_cast<unsigned*>(&h1);
    o.z = *reinterpret_cast<unsigned*>(&h2);
    o.w = *reinterpret_cast<unsigned*>(&h3);
    *reinterpret_cast<uint4*>(d + i) = o;
}

// ---------------- dtype probe (int64 vs int32 indices) ----------------
__global__ void detect_kernel(const int* __restrict__ idx32) {
    if (threadIdx.x == 0) {
        int a = 0;
        #pragma unroll 1
        for (int i = 0; i < 128; i++) a |= idx32[2 * i + 1];
        g_is64 = (a == 0) ? 1 : 0;
    }
}

// ---------------- deterministic per-expert pair lists ----------------
__global__ void build_lists(const int* __restrict__ idx32) {
    const int e = blockIdx.x;
    const bool is64 = (g_is64 != 0);
    __shared__ int wsum[8];
    __shared__ int sbase;
    const int tid = threadIdx.x, lane = tid & 31, w = tid >> 5;
    if (tid == 0) sbase = 0;
    __syncthreads();
    for (int st = 0; st < NPAIR; st += 256) {
        int p = st + tid;
        int v = is64 ? idx32[2 * p] : idx32[p];
        bool m = (v == e);
        unsigned bal = __ballot_sync(0xffffffffu, m);
        int within = __popc(bal & ((1u << lane) - 1u));
        if (lane == 0) wsum[w] = __popc(bal);
        __syncthreads();
        int off = sbase;
        for (int i = 0; i < w; i++) off += wsum[i];
        if (m) g_list[e * NPAIR + off + within] = p;
        __syncthreads();
        if (tid == 0) {
            int tot = 0;
            for (int i = 0; i < 8; i++) tot += wsum[i];
            sbase += tot;
        }
        __syncthreads();
    }
    if (tid == 0) g_cnt[e] = sbase;
}

__global__ void prefix_kernel() {
    if (threadIdx.x == 0) {
        g_cnt[16] = T_;
        g_cnt[17] = T_;
        int off = 0;
        for (int e = 0; e < NE2; e++) {
            g_offpad[e] = off;
            off += ((g_cnt[e] + BM - 1) / BM) * BM;
        }
        g_offpad[NE2] = off;
    }
}

// ---------------- wmma types (fp16 in, fp32 accum) ----------------
typedef wmma::fragment<wmma::matrix_a, 16, 16, 16, __half, wmma::row_major> FA;
typedef wmma::fragment<wmma::matrix_b, 16, 16, 16, __half, wmma::row_major> FB;
typedef wmma::fragment<wmma::accumulator, 16, 16, 16, float> FC;

// =====================================================================
// up kernel: H[rows] = silu(A@B1) * (A@B3).  256 threads, 8 warps.
// e < 16:  routed expert, A rows gathered via g_list, B = W1/W3[e].
// e >= 16: shared pseudo-expert h=e-16, A rows dense, B = Ws1/Ws3 column
//          slice [h*INTER, (h+1)*INTER) with ldB = SINTER.
// Output always g_Hh (row stride INTER_) at g_offpad[e].
// =====================================================================
__global__ void __launch_bounds__(256, 1)
up_kernel()
{
    constexpr int KT = DIM_ / BK;     // 64
    const int e = blockIdx.z;
    const int cnt = g_cnt[e];
    if ((int)blockIdx.y * BM >= cnt) return;
    const int hbase = g_offpad[e] + blockIdx.y * BM;
    const bool routed = (e < NE_);

    const __half* B1;
    const __half* B3;
    size_t ldB;
    if (routed) {
        B1 = g_W1h + (size_t)e * DIM_ * INTER_;
        B3 = g_W3h + (size_t)e * DIM_ * INTER_;
        ldB = INTER_;
    } else {
        B1 = g_Ws1h + (size_t)(e - NE_) * INTER_;
        B3 = g_Ws3h + (size_t)(e - NE_) * INTER_;
        ldB = SINTER_;
    }
    const int n0 = blockIdx.x * BN_UP;

    extern __shared__ __half sm[];
    __half* sA  = sm;                                  // [S][BM][BKP]
    __half* sB1 = sm + STAGES * BM * BKP;              // [S][BK][BNPU]
    __half* sB3 = sB1 + STAGES * BK * BNPU;

    const int tid  = threadIdx.x;
    const int warp = tid >> 5;
    const int grp  = warp >> 2;        // 0: W1, 1: W3
    const int wl   = warp & 3;
    const int wm   = wl & 1;           // 2 warps in M (64 rows)
    const int wn   = wl >> 1;          // 2 warps in N (64 cols)

    // ---- A copy: 128x32 halves = 512 chunks, 2 per thread
    const __half* aptr[2];
    uint32_t asoff[2];
    #pragma unroll
    for (int i = 0; i < 2; i++) {
        int id  = tid + 256 * i;
        int r   = id >> 2;
        int c8  = (id & 3) * 8;
        int row = blockIdx.y * BM + r;
        int tok;
        if (routed) tok = (row < cnt) ? (g_list[e * NPAIR + row] / TOPK_) : 0;
        else        tok = (row < cnt) ? row : 0;
        aptr[i]  = g_Xh + (size_t)tok * DIM_ + c8;
        asoff[i] = r * BKP + c8;
    }

    // ---- B copy: per matrix 32x128 halves = 512 chunks; threads 0-127 -> B1,
    // 128-255 -> B3, 4 chunks each
    const int bmat = tid >> 7;
    const __half* bsrcM = bmat ? B3 : B1;
    __half* bdst = bmat ? sB3 : sB1;
    const __half* bptr[4];
    uint32_t bsoff[4];
    #pragma unroll
    for (int i = 0; i < 4; i++) {
        int id = (tid & 127) + 128 * i;
        int r  = id >> 4;
        int c8 = (id & 15) * 8;
        bptr[i]  = bsrcM + (size_t)r * ldB + n0 + c8;
        bsoff[i] = r * BNPU + c8;
    }

    auto copy_stage = [&](int kt, int st) {
        const int k0 = kt * BK;
        #pragma unroll
        for (int i = 0; i < 2; i++)
            cpa16(&sA[st * BM * BKP + asoff[i]], aptr[i] + k0);
        #pragma unroll
        for (int i = 0; i < 4; i++)
            cpa16(&bdst[st * BK * BNPU + bsoff[i]], bptr[i] + (size_t)k0 * ldB);
    };

    FC acc[4][4];
    #pragma unroll
    for (int mi = 0; mi < 4; mi++)
        #pragma unroll
        for (int ni = 0; ni < 4; ni++) wmma::fill_fragment(acc[mi][ni], 0.f);

    const __half* sBg = grp ? sB3 : sB1;

    #pragma unroll
    for (int s = 0; s < STAGES - 1; s++) { copy_stage(s, s); CP_COMMIT(); }

    for (int kt = 0; kt < KT; kt++) {
        CP_WAIT(STAGES - 2);
        __syncthreads();
        int nk = kt + STAGES - 1;
        if (nk < KT) copy_stage(nk, nk % STAGES);
        CP_COMMIT();
        const int st = kt % STAGES;
        #pragma unroll
        for (int kk = 0; kk < BK; kk += 16) {
            FA fa[4];
            FB fb[4];
            #pragma unroll
            for (int mi = 0; mi < 4; mi++)
                wmma::load_matrix_sync(fa[mi], &sA[(st * BM + wm * 64 + mi * 16) * BKP + kk], BKP);
            #pragma unroll
            for (int ni = 0; ni < 4; ni++)
                wmma::load_matrix_sync(fb[ni], &sBg[(st * BK + kk) * BNPU + wn * 64 + ni * 16], BNPU);
            #pragma unroll
            for (int mi = 0; mi < 4; mi++)
                #pragma unroll
                for (int ni = 0; ni < 4; ni++)
                    wmma::mma_sync(acc[mi][ni], fa[mi], fb[ni], acc[mi][ni]);
        }
    }

    // ---- epilogue: dump both groups' accs to smem floats, fuse, store fp16 H
    CP_WAIT(0);
    __syncthreads();
    float* sF  = (float*)sm;                  // [2][BM][FP_ST]
    float* sFm = sF + grp * (BM * FP_ST);
    #pragma unroll
    for (int mi = 0; mi < 4; mi++)
        #pragma unroll
        for (int ni = 0; ni < 4; ni++)
            wmma::store_matrix_sync(&sFm[(wm * 64 + mi * 16) * FP_ST + wn * 64 + ni * 16],
                                    acc[mi][ni], FP_ST, wmma::mem_row_major);
    __syncthreads();

    {
        const int row = tid >> 1;
        const int seg = (tid & 1) * 64;
        const float* p1 = &sF[row * FP_ST + seg];
        const float* p3 = p1 + BM * FP_ST;
        __half* dst = g_Hh + (size_t)(hbase + row) * INTER_ + n0 + seg;
        #pragma unroll
        for (int c = 0; c < 64; c += 16) {
            __align__(16) __half hbuf[16];
            #pragma unroll
            for (int j = 0; j < 16; j++) {
                float u = p1[c + j];
                float s = u / (1.f + __expf(-u));
                hbuf[j] = __float2half_rn(s * p3[c + j]);
            }
            *(uint4*)(dst + c)     = *(uint4*)(hbuf);
            *(uint4*)(dst + c + 8) = *(uint4*)(hbuf + 8);
        }
    }
}

// =====================================================================
// down kernel: Y = H @ B.  128 threads, 4 warps (2x2 of 64x64), 2 CTAs/SM.
// K = INTER_ uniformly.  e<16: B = W2[e], scatter to slot t*8+k scaled by
// routing weight.  e>=16: B = Ws2 rows [h*INTER,(h+1)*INTER), slot t*8+6+h, w=1.
// =====================================================================
__global__ void __launch_bounds__(128, 2)
down_kernel(const float* __restrict__ wts)
{
    constexpr int KT = INTER_ / BK;   // 44
    const int e = blockIdx.z;
    const int cnt = g_cnt[e];
    if ((int)blockIdx.y * BM >= cnt) return;
    const int abase = g_offpad[e] + blockIdx.y * BM;
    const bool routed = (e < NE_);

    const __half* Bh = routed ? (g_W2h + (size_t)e * INTER_ * DIM_)
                              : (g_Ws2h + (size_t)(e - NE_) * INTER_ * DIM_);
    const int n0 = blockIdx.x * BND;

    extern __shared__ __half sm[];
    __half* sA = sm;                                // [S][BM][BKP]
    __half* sB = sm + STAGES * BM * BKP;            // [S][BK][BNDP]

    const int tid  = threadIdx.x;
    const int warp = tid >> 5;
    const int wm   = warp & 1;
    const int wn   = warp >> 1;

    const __half* aptr[4];
    uint32_t asoff[4];
    #pragma unroll
    for (int i = 0; i < 4; i++) {
        int id = tid + 128 * i;
        int r  = id >> 2;
        int c8 = (id & 3) * 8;
        aptr[i]  = g_Hh + (size_t)(abase + r) * INTER_ + c8;
        asoff[i] = r * BKP + c8;
    }
    const __half* bptr[4];
    uint32_t bsoff[4];
    #pragma unroll
    for (int i = 0; i < 4; i++) {
        int id = tid + 128 * i;
        int r  = id >> 4;
        int c8 = (id & 15) * 8;
        bptr[i]  = Bh + (size_t)r * DIM_ + n0 + c8;
        bsoff[i] = r * BNDP + c8;
    }

    auto copy_stage = [&](int kt, int st) {
        const int k0 = kt * BK;
        #pragma unroll
        for (int i = 0; i < 4; i++)
            cpa16(&sA[st * BM * BKP + asoff[i]], aptr[i] + k0);
        #pragma unroll
        for (int i = 0; i < 4; i++)
            cpa16(&sB[st * BK * BNDP + bsoff[i]], bptr[i] + (size_t)k0 * DIM_);
    };

    FC acc[4][4];
    #pragma unroll
    for (int mi = 0; mi < 4; mi++)
        #pragma unroll
        for (int ni = 0; ni < 4; ni++) wmma::fill_fragment(acc[mi][ni], 0.f);

    #pragma unroll
    for (int s = 0; s < STAGES - 1; s++) { copy_stage(s, s); CP_COMMIT(); }

    for (int kt = 0; kt < KT; kt++) {
        CP_WAIT(STAGES - 2);
        __syncthreads();
        int nk = kt + STAGES - 1;
        if (nk < KT) copy_stage(nk, nk % STAGES);
        CP_COMMIT();
        const int st = kt % STAGES;
        #pragma unroll
        for (int kk = 0; kk < BK; kk += 16) {
            FA fa[4];
            FB fb[4];
            #pragma unroll
            for (int mi = 0; mi < 4; mi++)
                wmma::load_matrix_sync(fa[mi], &sA[(st * BM + wm * 64 + mi * 16) * BKP + kk], BKP);
            #pragma unroll
            for (int ni = 0; ni < 4; ni++)
                wmma::load_matrix_sync(fb[ni], &sB[(st * BK + kk) * BNDP + wn * 64 + ni * 16], BNDP);
            #pragma unroll
            for (int mi = 0; mi < 4; mi++)
                #pragma unroll
                for (int ni = 0; ni < 4; ni++)
                    wmma::mma_sync(acc[mi][ni], fa[mi], fb[ni], acc[mi][ni]);
        }
    }

    CP_WAIT(0);
    __syncthreads();
    float* sF = (float*)sm;                   // [BM][FP_ST]
    #pragma unroll
    for (int mi = 0; mi < 4; mi++)
        #pragma unroll
        for (int ni = 0; ni < 4; ni++)
            wmma::store_matrix_sync(&sF[(wm * 64 + mi * 16) * FP_ST + wn * 64 + ni * 16],
                                    acc[mi][ni], FP_ST, wmma::mem_row_major);
    __syncthreads();

    {
        const int row = tid;                  // one row per thread
        const float* src = &sF[row * FP_ST];
        const int gslot = blockIdx.y * BM + row;
        if (gslot < cnt) {
            int slot;
            float w;
            if (routed) {
                int p = g_list[e * NPAIR + gslot];
                int t = p / TOPK_;
                int k = p - t * TOPK_;
                slot = t * NSLOT + k;
                w = wts[p];
            } else {
                slot = gslot * NSLOT + TOPK_ + (e - NE_);
                w = 1.f;
            }
            float* dst = g_Yb + (size_t)slot * DIM_ + n0;
            #pragma unroll
            for (int j = 0; j < 128; j += 4) {
                float4 v = *(const float4*)(src + j);
                v.x *= w; v.y *= w; v.z *= w; v.w *= w;
                *(float4*)(dst + j) = v;
            }
        }
    }
}

// ---------------- final reduction: out[t] = sum over 8 slots ----------------
__global__ void __launch_bounds__(256, 1) reduce_kernel(float* __restrict__ out) {
    int i = blockIdx.x * 256 + threadIdx.x;
    const int row4 = DIM_ / 4;
    int t  = i / row4;
    int c4 = i % row4;
    const float* base = g_Yb + (size_t)t * NSLOT * DIM_ + c4 * 4;
    float4 a = *(const float4*)(base);
    #pragma unroll
    for (int k = 1; k < NSLOT; k++) {
        const float4 v = *(const float4*)(base + (size_t)k * DIM_);
        a.x += v.x; a.y += v.y; a.z += v.z; a.w += v.w;
    }
    ((float4*)out)[i] = a;
}

// ---------------- launch ----------------
extern "C" void kernel_launch(void* const* d_in, const int* in_sizes, int n_in,
                              void* d_out, int out_size) {
    const float* x   = (const float*)d_in[0];
    const float* wts = (const float*)d_in[1];
    const int*   idx = (const int*)  d_in[2];
    const float* W1  = (const float*)d_in[3];
    const float* W3  = (const float*)d_in[4];
    const float* W2  = (const float*)d_in[5];
    const float* Ws1 = (const float*)d_in[6];
    const float* Ws3 = (const float*)d_in[7];
    const float* Ws2 = (const float*)d_in[8];
    float* out = (float*)d_out;

    cudaFuncSetAttribute(up_kernel,   cudaFuncAttributeMaxDynamicSharedMemorySize, UP_SMEM_B);
    cudaFuncSetAttribute(down_kernel, cudaFuncAttributeMaxDynamicSharedMemorySize, DOWN_SMEM_B);

    void *pW1h, *pW3h, *pW2h, *pWs1h, *pWs3h, *pWs2h, *pXh;
    cudaGetSymbolAddress(&pW1h,  g_W1h);
    cudaGetSymbolAddress(&pW3h,  g_W3h);
    cudaGetSymbolAddress(&pW2h,  g_W2h);
    cudaGetSymbolAddress(&pWs1h, g_Ws1h);
    cudaGetSymbolAddress(&pWs3h, g_Ws3h);
    cudaGetSymbolAddress(&pWs2h, g_Ws2h);
    cudaGetSymbolAddress(&pXh,   g_Xh);

    auto cvt = [&](const float* s, void* d, long long n) {
        int blocks = (int)((n + 2047) / 2048);
        cvt_kernel<<<blocks, 256>>>(s, (__half*)d, (int)n);
    };
    const long long nW  = (long long)NE_ * DIM_ * INTER_;
    const long long nWs = (long long)DIM_ * SINTER_;
    cvt(x,   pXh,   (long long)T_ * DIM_);
    cvt(W1,  pW1h,  nW);
    cvt(W3,  pW3h,  nW);
    cvt(W2,  pW2h,  nW);
    cvt(Ws1, pWs1h, nWs);
    cvt(Ws3, pWs3h, nWs);
    cvt(Ws2, pWs2h, nWs);

    detect_kernel<<<1, 32>>>(idx);
    build_lists<<<NE_, 256>>>(idx);
    prefix_kernel<<<1, 32>>>();

    // unified up: routed experts (z<16) + shared pseudo-experts (z=16,17)
    up_kernel<<<dim3(INTER_ / BN_UP, NPAIR / BM, NE2), 256, UP_SMEM_B>>>();
    // unified down: K = INTER for all
    down_kernel<<<dim3(DIM_ / BND, NPAIR / BM, NE2), 128, DOWN_SMEM_B>>>(wts);
    // out[t] = sum over 8 slots
    reduce_kernel<<<(T_ * DIM_ / 4) / 256, 256>>>(out);
}